// round 2
// baseline (speedup 1.0000x reference)
#include <cuda_runtime.h>
#include <cuda_bf16.h>
#include <cstdint>

#define NMAX 50000
#define EMAX 800000

// ---------------- scratch (static device globals; no allocation) ----------------
__device__ __align__(16) float d_A1[NMAX * 128];
__device__ __align__(16) float d_B1[NMAX * 128];
__device__ __align__(16) float d_s1[NMAX * 128];
__device__ __align__(16) float d_h [NMAX * 128];
__device__ __align__(16) float d_A2[NMAX * 64];
__device__ __align__(16) float d_B2[NMAX * 64];
__device__ __align__(16) float d_s2[NMAX * 64];
__device__ __align__(16) float d_g [NMAX * 64];
__device__ __align__(16) float d_xin[NMAX * 144];
__device__ __align__(16) float d_x1[NMAX * 256];
__device__ __align__(16) float d_x2[NMAX * 256];
__device__ int   d_cnt[NMAX];
__device__ int   d_off[NMAX + 1];
__device__ int   d_cur[NMAX];
__device__ int   d_srcs[EMAX];

// ---------------- CSR build ----------------
__global__ void hist_kernel(const int* __restrict__ dst, int* __restrict__ cnt, int E, int N)
{
    int e = blockIdx.x * blockDim.x + threadIdx.x;
    if (e < E) {
        int d = dst[e];
        d = min(max(d, 0), N - 1);
        atomicAdd(&cnt[d], 1);
    }
}

// single-block exclusive scan (N up to 50k: ~49 tiles of 1024)
__global__ void scan_kernel(const int* __restrict__ cnt, int* __restrict__ off, int n)
{
    __shared__ int sh[1024];
    int tid = threadIdx.x;
    int carry = 0;
    for (int base = 0; base < n; base += 1024) {
        int i = base + tid;
        int v = (i < n) ? cnt[i] : 0;
        sh[tid] = v;
        __syncthreads();
        #pragma unroll
        for (int d = 1; d < 1024; d <<= 1) {
            int t = (tid >= d) ? sh[tid - d] : 0;
            __syncthreads();
            sh[tid] += t;
            __syncthreads();
        }
        if (i < n) off[i] = carry + sh[tid] - v;   // exclusive
        int tileSum = sh[1023];
        __syncthreads();
        carry += tileSum;
    }
    if (tid == 0) off[n] = carry;
}

__global__ void scatter_kernel(const int* __restrict__ src, const int* __restrict__ dst,
                               const int* __restrict__ off, int* __restrict__ cur,
                               int* __restrict__ out, int E, int N)
{
    int e = blockIdx.x * blockDim.x + threadIdx.x;
    if (e < E) {
        int d = dst[e];
        d = min(max(d, 0), N - 1);
        int s = src[e];
        s = min(max(s, 0), N - 1);
        int p = atomicAdd(&cur[d], 1);
        out[off[d] + p] = s;
    }
}

// ---------------- edge aggregation: s[i] = (1/max(cnt,1)) * sum_{src in adj(i)} relu(A[i] + B[src]) ----------------
__global__ void aggregate128(const float* __restrict__ A, const float* __restrict__ B,
                             const int* __restrict__ off, const int* __restrict__ srcs,
                             float* __restrict__ S, int n)
{
    int gw = (int)((blockIdx.x * blockDim.x + threadIdx.x) >> 5);
    int lane = threadIdx.x & 31;
    if (gw >= n) return;
    const float4* A4 = reinterpret_cast<const float4*>(A);
    const float4* B4 = reinterpret_cast<const float4*>(B);
    float4 a = A4[(size_t)gw * 32 + lane];
    float4 acc = make_float4(0.f, 0.f, 0.f, 0.f);
    int s = off[gw], e = off[gw + 1];
    for (int base = s; base < e; base += 32) {
        int m = e - base; if (m > 32) m = 32;
        int idx = (lane < m) ? srcs[base + lane] : 0;
        for (int j = 0; j < m; j++) {
            int sj = __shfl_sync(0xffffffffu, idx, j);
            float4 b = B4[(size_t)sj * 32 + lane];
            acc.x += fmaxf(a.x + b.x, 0.f);
            acc.y += fmaxf(a.y + b.y, 0.f);
            acc.z += fmaxf(a.z + b.z, 0.f);
            acc.w += fmaxf(a.w + b.w, 0.f);
        }
    }
    float inv = 1.f / fmaxf((float)(e - s), 1.f);
    float4 o = make_float4(acc.x * inv, acc.y * inv, acc.z * inv, acc.w * inv);
    reinterpret_cast<float4*>(S)[(size_t)gw * 32 + lane] = o;
}

__global__ void aggregate64(const float* __restrict__ A, const float* __restrict__ B,
                            const int* __restrict__ off, const int* __restrict__ srcs,
                            float* __restrict__ S, int n)
{
    int gw = (int)((blockIdx.x * blockDim.x + threadIdx.x) >> 5);
    int lane = threadIdx.x & 31;
    if (gw >= n) return;
    const float2* A2p = reinterpret_cast<const float2*>(A);
    const float2* B2p = reinterpret_cast<const float2*>(B);
    float2 a = A2p[(size_t)gw * 32 + lane];
    float2 acc = make_float2(0.f, 0.f);
    int s = off[gw], e = off[gw + 1];
    for (int base = s; base < e; base += 32) {
        int m = e - base; if (m > 32) m = 32;
        int idx = (lane < m) ? srcs[base + lane] : 0;
        for (int j = 0; j < m; j++) {
            int sj = __shfl_sync(0xffffffffu, idx, j);
            float2 b = B2p[(size_t)sj * 32 + lane];
            acc.x += fmaxf(a.x + b.x, 0.f);
            acc.y += fmaxf(a.y + b.y, 0.f);
        }
    }
    float inv = 1.f / fmaxf((float)(e - s), 1.f);
    float2 o = make_float2(acc.x * inv, acc.y * inv);
    reinterpret_cast<float2*>(S)[(size_t)gw * 32 + lane] = o;
}

// ---------------- tiled fp32 GEMM: C = act(X[M,K] @ W[K,NOUT] + bias(gated)) ----------------
// Requirements: K % 16 == 0, NOUT % 64 == 0 (true for all uses here).
__global__ __launch_bounds__(256) void gemm_kernel(
    const float* __restrict__ X, const float* __restrict__ W,
    const float* __restrict__ bias, const int* __restrict__ cnt,
    float* __restrict__ C, int M, int K, int NOUT, int doRelu)
{
    __shared__ float Xs[16][68];
    __shared__ float Ws[16][68];
    int t  = threadIdx.x;
    int tx = t & 15;
    int ty = t >> 4;
    int rowBase = blockIdx.y * 64;
    int colBase = blockIdx.x * 64;

    float acc[4][4];
    #pragma unroll
    for (int i = 0; i < 4; i++)
        #pragma unroll
        for (int j = 0; j < 4; j++) acc[i][j] = 0.f;

    int r  = t >> 2;            // 0..63 row within tile (for X load)
    int kq = (t & 3) * 4;       // 0,4,8,12
    int kr = t >> 4;            // 0..15 (for W load)
    int c4 = (t & 15) * 4;      // 0..60

    for (int k0 = 0; k0 < K; k0 += 16) {
        float4 xv;
        int grow = rowBase + r;
        if (grow < M) xv = *reinterpret_cast<const float4*>(X + (size_t)grow * K + k0 + kq);
        else          xv = make_float4(0.f, 0.f, 0.f, 0.f);
        Xs[kq + 0][r] = xv.x; Xs[kq + 1][r] = xv.y; Xs[kq + 2][r] = xv.z; Xs[kq + 3][r] = xv.w;

        float4 wv = *reinterpret_cast<const float4*>(W + (size_t)(k0 + kr) * NOUT + colBase + c4);
        Ws[kr][c4 + 0] = wv.x; Ws[kr][c4 + 1] = wv.y; Ws[kr][c4 + 2] = wv.z; Ws[kr][c4 + 3] = wv.w;
        __syncthreads();

        #pragma unroll
        for (int kk = 0; kk < 16; kk++) {
            float4 xr = *reinterpret_cast<const float4*>(&Xs[kk][ty * 4]);
            float4 wr = *reinterpret_cast<const float4*>(&Ws[kk][tx * 4]);
            acc[0][0] += xr.x * wr.x; acc[0][1] += xr.x * wr.y; acc[0][2] += xr.x * wr.z; acc[0][3] += xr.x * wr.w;
            acc[1][0] += xr.y * wr.x; acc[1][1] += xr.y * wr.y; acc[1][2] += xr.y * wr.z; acc[1][3] += xr.y * wr.w;
            acc[2][0] += xr.z * wr.x; acc[2][1] += xr.z * wr.y; acc[2][2] += xr.z * wr.z; acc[2][3] += xr.z * wr.w;
            acc[3][0] += xr.w * wr.x; acc[3][1] += xr.w * wr.y; acc[3][2] += xr.w * wr.z; acc[3][3] += xr.w * wr.w;
        }
        __syncthreads();
    }

    #pragma unroll
    for (int i = 0; i < 4; i++) {
        int row = rowBase + ty * 4 + i;
        if (row >= M) continue;
        float gate = 1.f;
        if (cnt) gate = (cnt[row] > 0) ? 1.f : 0.f;
        #pragma unroll
        for (int j = 0; j < 4; j++) {
            int col = colBase + tx * 4 + j;
            float v = acc[i][j];
            if (bias) v += bias[col] * gate;
            if (doRelu) v = fmaxf(v, 0.f);
            C[(size_t)row * NOUT + col] = v;
        }
    }
}

// ---------------- concat: xin = [state(64) | g(64) | emb[mode](16)] ----------------
__global__ void concat_kernel(const float* __restrict__ state, const float* __restrict__ g,
                              const float* __restrict__ emb, const int* __restrict__ mode,
                              float* __restrict__ xin, int n)
{
    int i = blockIdx.x * blockDim.x + threadIdx.x;
    int total = n * 144;
    if (i >= total) return;
    int node = i / 144;
    int c = i - node * 144;
    float v;
    if (c < 64)       v = state[(size_t)node * 64 + c];
    else if (c < 128) v = g[(size_t)node * 64 + (c - 64)];
    else {
        int m = mode[node];
        m = min(max(m, 0), 2);
        v = emb[(size_t)m * 16 + (c - 128)];
    }
    xin[i] = v;
}

// ---------------- heads: mean = x2@wm+bm ; log_std = clip(x2@ws+bs, -20, 2) ----------------
__global__ __launch_bounds__(256) void heads_kernel(
    const float* __restrict__ x2,
    const float* __restrict__ wm, const float* __restrict__ bm,
    const float* __restrict__ ws, const float* __restrict__ bs,
    float* __restrict__ out_mean, float* __restrict__ out_ls, int n)
{
    __shared__ float WmT[8 * 256];   // [o][k]
    __shared__ float WsT[8 * 256];
    for (int i = threadIdx.x; i < 2048; i += blockDim.x) {
        int o = i >> 8;
        int k = i & 255;
        WmT[i] = wm[k * 8 + o];
        WsT[i] = ws[k * 8 + o];
    }
    __syncthreads();
    int lane = threadIdx.x & 31;
    int w = threadIdx.x >> 5;
    int warpsPerBlock = blockDim.x >> 5;
    for (int node = blockIdx.x * warpsPerBlock + w; node < n; node += gridDim.x * warpsPerBlock) {
        float xv[8];
        #pragma unroll
        for (int c = 0; c < 8; c++) xv[c] = x2[(size_t)node * 256 + c * 32 + lane];
        float accM[8], accS[8];
        #pragma unroll
        for (int o = 0; o < 8; o++) { accM[o] = 0.f; accS[o] = 0.f; }
        #pragma unroll
        for (int c = 0; c < 8; c++) {
            int k = c * 32 + lane;
            #pragma unroll
            for (int o = 0; o < 8; o++) {
                accM[o] += xv[c] * WmT[o * 256 + k];
                accS[o] += xv[c] * WsT[o * 256 + k];
            }
        }
        #pragma unroll
        for (int o = 0; o < 8; o++) {
            #pragma unroll
            for (int d = 16; d > 0; d >>= 1) {
                accM[o] += __shfl_xor_sync(0xffffffffu, accM[o], d);
                accS[o] += __shfl_xor_sync(0xffffffffu, accS[o], d);
            }
        }
        if (lane == 0) {
            #pragma unroll
            for (int o = 0; o < 8; o++) {
                out_mean[(size_t)node * 8 + o] = accM[o] + bm[o];
                float lsv = accS[o] + bs[o];
                lsv = fminf(fmaxf(lsv, -20.f), 2.f);
                out_ls[(size_t)node * 8 + o] = lsv;
            }
        }
    }
}

// ---------------- launch ----------------
extern "C" void kernel_launch(void* const* d_in, const int* in_sizes, int n_in,
                              void* d_out, int out_size)
{
    const float* state  = (const float*)d_in[0];
    const float* xnodes = (const float*)d_in[1];
    const int*   edge   = (const int*)d_in[2];     // int32 (JAX x64 disabled coerces int64->int32)
    const int*   mode   = (const int*)d_in[3];
    const float* w_g1a = (const float*)d_in[4];
    const float* b_g1a = (const float*)d_in[5];
    const float* w_g1b = (const float*)d_in[6];
    const float* b_g1b = (const float*)d_in[7];
    const float* w_g2a = (const float*)d_in[8];
    const float* b_g2a = (const float*)d_in[9];
    const float* w_g2b = (const float*)d_in[10];
    const float* b_g2b = (const float*)d_in[11];
    const float* emb   = (const float*)d_in[12];
    const float* w1    = (const float*)d_in[13];
    const float* b1    = (const float*)d_in[14];
    const float* w2    = (const float*)d_in[15];
    const float* b2    = (const float*)d_in[16];
    const float* wm    = (const float*)d_in[17];
    const float* bm    = (const float*)d_in[18];
    const float* ws    = (const float*)d_in[19];
    const float* bs    = (const float*)d_in[20];

    const int N = in_sizes[0] / 64;     // 50000
    const int E = in_sizes[2] / 2;      // 800000
    const int* src = edge;
    const int* dst = edge + E;

    float *A1, *B1, *s1, *h, *A2, *B2, *s2, *g, *xin, *x1, *x2;
    int *cnt, *off, *cur, *srcs;
    cudaGetSymbolAddress((void**)&A1,   d_A1);
    cudaGetSymbolAddress((void**)&B1,   d_B1);
    cudaGetSymbolAddress((void**)&s1,   d_s1);
    cudaGetSymbolAddress((void**)&h,    d_h);
    cudaGetSymbolAddress((void**)&A2,   d_A2);
    cudaGetSymbolAddress((void**)&B2,   d_B2);
    cudaGetSymbolAddress((void**)&s2,   d_s2);
    cudaGetSymbolAddress((void**)&g,    d_g);
    cudaGetSymbolAddress((void**)&xin,  d_xin);
    cudaGetSymbolAddress((void**)&x1,   d_x1);
    cudaGetSymbolAddress((void**)&x2,   d_x2);
    cudaGetSymbolAddress((void**)&cnt,  d_cnt);
    cudaGetSymbolAddress((void**)&off,  d_off);
    cudaGetSymbolAddress((void**)&cur,  d_cur);
    cudaGetSymbolAddress((void**)&srcs, d_srcs);

    float* out_mean = (float*)d_out;
    float* out_ls   = (float*)d_out + (size_t)N * 8;

    // --- CSR by dst ---
    cudaMemsetAsync(cnt, 0, N * sizeof(int), 0);
    cudaMemsetAsync(cur, 0, N * sizeof(int), 0);
    hist_kernel<<<(E + 255) / 256, 256>>>(dst, cnt, E, N);
    scan_kernel<<<1, 1024>>>(cnt, off, N);
    scatter_kernel<<<(E + 255) / 256, 256>>>(src, dst, off, cur, srcs, E, N);

    dim3 tpb(256);
    int mBlocks = (N + 63) / 64;

    // --- Layer 1: A1 = x@wa[0:64] + ba ; B1 = x@wa[64:128] ---
    gemm_kernel<<<dim3(128 / 64, mBlocks), tpb>>>(xnodes, w_g1a,            b_g1a, nullptr, A1, N, 64, 128, 0);
    gemm_kernel<<<dim3(128 / 64, mBlocks), tpb>>>(xnodes, w_g1a + 64 * 128, nullptr, nullptr, B1, N, 64, 128, 0);
    aggregate128<<<(N * 32 + 255) / 256, 256>>>(A1, B1, off, srcs, s1, N);
    // h = relu(s1 @ w_g1b + gated b_g1b)
    gemm_kernel<<<dim3(128 / 64, mBlocks), tpb>>>(s1, w_g1b, b_g1b, cnt, h, N, 128, 128, 1);

    // --- Layer 2: A2 = h@w2a[0:128] + b2a ; B2 = h@w2a[128:256] ---
    gemm_kernel<<<dim3(64 / 64, mBlocks), tpb>>>(h, w_g2a,             b_g2a, nullptr, A2, N, 128, 64, 0);
    gemm_kernel<<<dim3(64 / 64, mBlocks), tpb>>>(h, w_g2a + 128 * 64,  nullptr, nullptr, B2, N, 128, 64, 0);
    aggregate64<<<(N * 32 + 255) / 256, 256>>>(A2, B2, off, srcs, s2, N);
    // g = s2 @ w_g2b + gated b_g2b (no relu)
    gemm_kernel<<<dim3(64 / 64, mBlocks), tpb>>>(s2, w_g2b, b_g2b, cnt, g, N, 64, 64, 0);

    // --- MLP head ---
    concat_kernel<<<(N * 144 + 255) / 256, 256>>>(state, g, emb, mode, xin, N);
    gemm_kernel<<<dim3(256 / 64, mBlocks), tpb>>>(xin, w1, b1, nullptr, x1, N, 144, 256, 1);
    gemm_kernel<<<dim3(256 / 64, mBlocks), tpb>>>(x1,  w2, b2, nullptr, x2, N, 256, 256, 1);
    heads_kernel<<<(N + 7) / 8, 256>>>(x2, wm, bm, ws, bs, out_mean, out_ls, N);
}

// round 3
// speedup vs baseline: 1.0405x; 1.0405x over previous
#include <cuda_runtime.h>
#include <cuda_bf16.h>
#include <cstdint>

#define NMAX 50000
#define EMAX 800000

// ---------------- scratch (static device globals; no allocation) ----------------
__device__ __align__(16) float d_A1[NMAX * 128];
__device__ __align__(16) float d_B1[NMAX * 128];
__device__ __align__(16) float d_s1[NMAX * 128];
__device__ __align__(16) float d_h [NMAX * 128];
__device__ __align__(16) float d_A2[NMAX * 64];
__device__ __align__(16) float d_B2[NMAX * 64];
__device__ __align__(16) float d_s2[NMAX * 64];
__device__ __align__(16) float d_g [NMAX * 64];
__device__ __align__(16) float d_xin[NMAX * 144];
__device__ __align__(16) float d_x1[NMAX * 256];
__device__ __align__(16) float d_x2[NMAX * 256];
__device__ int   d_cnt[NMAX];
__device__ int   d_off[NMAX + 1];
__device__ int   d_cur[NMAX];
__device__ int   d_srcs[EMAX];

// ---------------- CSR build ----------------
__global__ void hist_kernel(const int* __restrict__ dst, int* __restrict__ cnt, int E, int N)
{
    int e = blockIdx.x * blockDim.x + threadIdx.x;
    if (e < E) {
        int d = dst[e];
        d = min(max(d, 0), N - 1);
        atomicAdd(&cnt[d], 1);
    }
}

__global__ void scan_kernel(const int* __restrict__ cnt, int* __restrict__ off, int n)
{
    __shared__ int sh[1024];
    int tid = threadIdx.x;
    int carry = 0;
    for (int base = 0; base < n; base += 1024) {
        int i = base + tid;
        int v = (i < n) ? cnt[i] : 0;
        sh[tid] = v;
        __syncthreads();
        #pragma unroll
        for (int d = 1; d < 1024; d <<= 1) {
            int t = (tid >= d) ? sh[tid - d] : 0;
            __syncthreads();
            sh[tid] += t;
            __syncthreads();
        }
        if (i < n) off[i] = carry + sh[tid] - v;   // exclusive
        int tileSum = sh[1023];
        __syncthreads();
        carry += tileSum;
    }
    if (tid == 0) off[n] = carry;
}

__global__ void scatter_kernel(const int* __restrict__ src, const int* __restrict__ dst,
                               const int* __restrict__ off, int* __restrict__ cur,
                               int* __restrict__ out, int E, int N)
{
    int e = blockIdx.x * blockDim.x + threadIdx.x;
    if (e < E) {
        int d = dst[e];
        d = min(max(d, 0), N - 1);
        int s = src[e];
        s = min(max(s, 0), N - 1);
        int p = atomicAdd(&cur[d], 1);
        out[off[d] + p] = s;
    }
}

// ---------------- edge aggregation ----------------
__global__ void aggregate128(const float* __restrict__ A, const float* __restrict__ B,
                             const int* __restrict__ off, const int* __restrict__ srcs,
                             float* __restrict__ S, int n)
{
    int gw = (int)((blockIdx.x * blockDim.x + threadIdx.x) >> 5);
    int lane = threadIdx.x & 31;
    if (gw >= n) return;
    const float4* A4 = reinterpret_cast<const float4*>(A);
    const float4* B4 = reinterpret_cast<const float4*>(B);
    float4 a = A4[(size_t)gw * 32 + lane];
    float4 acc = make_float4(0.f, 0.f, 0.f, 0.f);
    int s = off[gw], e = off[gw + 1];
    for (int base = s; base < e; base += 32) {
        int m = e - base; if (m > 32) m = 32;
        int idx = (lane < m) ? srcs[base + lane] : 0;
        for (int j = 0; j < m; j++) {
            int sj = __shfl_sync(0xffffffffu, idx, j);
            float4 b = B4[(size_t)sj * 32 + lane];
            acc.x += fmaxf(a.x + b.x, 0.f);
            acc.y += fmaxf(a.y + b.y, 0.f);
            acc.z += fmaxf(a.z + b.z, 0.f);
            acc.w += fmaxf(a.w + b.w, 0.f);
        }
    }
    float inv = 1.f / fmaxf((float)(e - s), 1.f);
    float4 o = make_float4(acc.x * inv, acc.y * inv, acc.z * inv, acc.w * inv);
    reinterpret_cast<float4*>(S)[(size_t)gw * 32 + lane] = o;
}

__global__ void aggregate64(const float* __restrict__ A, const float* __restrict__ B,
                            const int* __restrict__ off, const int* __restrict__ srcs,
                            float* __restrict__ S, int n)
{
    int gw = (int)((blockIdx.x * blockDim.x + threadIdx.x) >> 5);
    int lane = threadIdx.x & 31;
    if (gw >= n) return;
    const float2* A2p = reinterpret_cast<const float2*>(A);
    const float2* B2p = reinterpret_cast<const float2*>(B);
    float2 a = A2p[(size_t)gw * 32 + lane];
    float2 acc = make_float2(0.f, 0.f);
    int s = off[gw], e = off[gw + 1];
    for (int base = s; base < e; base += 32) {
        int m = e - base; if (m > 32) m = 32;
        int idx = (lane < m) ? srcs[base + lane] : 0;
        for (int j = 0; j < m; j++) {
            int sj = __shfl_sync(0xffffffffu, idx, j);
            float2 b = B2p[(size_t)sj * 32 + lane];
            acc.x += fmaxf(a.x + b.x, 0.f);
            acc.y += fmaxf(a.y + b.y, 0.f);
        }
    }
    float inv = 1.f / fmaxf((float)(e - s), 1.f);
    float2 o = make_float2(acc.x * inv, acc.y * inv);
    reinterpret_cast<float2*>(S)[(size_t)gw * 32 + lane] = o;
}

// ---------------- GEMM v2: 128x64 tile, 8x4/thread, double-buffered smem ----------------
// C = act(X[M,K] @ W[K,NOUT] + bias(gated)).  K % 16 == 0, NOUT % 64 == 0.
__global__ __launch_bounds__(256) void gemm_kernel(
    const float* __restrict__ X, const float* __restrict__ W,
    const float* __restrict__ bias, const int* __restrict__ cnt,
    float* __restrict__ C, int M, int K, int NOUT, int doRelu)
{
    __shared__ float Xs[2][16][132];   // [buf][k][row], stride 132 (16B-aligned rows)
    __shared__ float Ws[2][16][72];    // [buf][k][col], stride 72  (16B-aligned rows)

    int t  = threadIdx.x;
    int tx = t & 15;            // col group: cols tx*4 .. tx*4+3
    int ty = t >> 4;            // row group: rows ty*8 .. ty*8+7
    int rowBase = blockIdx.y * 128;
    int colBase = blockIdx.x * 64;

    // loader mapping
    int lr = t & 127;           // X tile row
    int lk = (t >> 7) * 8;      // k offset within 16-step: 0 or 8
    int wk = t >> 4;            // W k-row 0..15
    int wc = (t & 15) * 4;      // W col offset

    const float* Xp = X + (size_t)(rowBase + lr) * K + lk;
    const float* Wp = W + (size_t)wk * NOUT + colBase + wc;
    bool xvalid = (rowBase + lr) < M;

    float4 xa, xb, wv;
    const float4 z4 = make_float4(0.f, 0.f, 0.f, 0.f);
    xa = xvalid ? *reinterpret_cast<const float4*>(Xp)     : z4;
    xb = xvalid ? *reinterpret_cast<const float4*>(Xp + 4) : z4;
    wv = *reinterpret_cast<const float4*>(Wp);

    float acc[8][4];
    #pragma unroll
    for (int i = 0; i < 8; i++)
        #pragma unroll
        for (int j = 0; j < 4; j++) acc[i][j] = 0.f;

    int nk = K >> 4;
    int buf = 0;
    for (int ki = 0; ki < nk; ki++) {
        // commit prefetched regs to smem[buf]
        Xs[buf][lk + 0][lr] = xa.x; Xs[buf][lk + 1][lr] = xa.y;
        Xs[buf][lk + 2][lr] = xa.z; Xs[buf][lk + 3][lr] = xa.w;
        Xs[buf][lk + 4][lr] = xb.x; Xs[buf][lk + 5][lr] = xb.y;
        Xs[buf][lk + 6][lr] = xb.z; Xs[buf][lk + 7][lr] = xb.w;
        *reinterpret_cast<float4*>(&Ws[buf][wk][wc]) = wv;
        __syncthreads();

        // prefetch next tile while computing this one
        if (ki + 1 < nk) {
            int k0 = (ki + 1) * 16;
            xa = xvalid ? *reinterpret_cast<const float4*>(Xp + k0)     : z4;
            xb = xvalid ? *reinterpret_cast<const float4*>(Xp + k0 + 4) : z4;
            wv = *reinterpret_cast<const float4*>(W + (size_t)(k0 + wk) * NOUT + colBase + wc);
        }

        #pragma unroll
        for (int kk = 0; kk < 16; kk++) {
            float4 x0 = *reinterpret_cast<const float4*>(&Xs[buf][kk][ty * 8]);
            float4 x1 = *reinterpret_cast<const float4*>(&Xs[buf][kk][ty * 8 + 4]);
            float4 wr = *reinterpret_cast<const float4*>(&Ws[buf][kk][tx * 4]);
            acc[0][0] += x0.x * wr.x; acc[0][1] += x0.x * wr.y; acc[0][2] += x0.x * wr.z; acc[0][3] += x0.x * wr.w;
            acc[1][0] += x0.y * wr.x; acc[1][1] += x0.y * wr.y; acc[1][2] += x0.y * wr.z; acc[1][3] += x0.y * wr.w;
            acc[2][0] += x0.z * wr.x; acc[2][1] += x0.z * wr.y; acc[2][2] += x0.z * wr.z; acc[2][3] += x0.z * wr.w;
            acc[3][0] += x0.w * wr.x; acc[3][1] += x0.w * wr.y; acc[3][2] += x0.w * wr.z; acc[3][3] += x0.w * wr.w;
            acc[4][0] += x1.x * wr.x; acc[4][1] += x1.x * wr.y; acc[4][2] += x1.x * wr.z; acc[4][3] += x1.x * wr.w;
            acc[5][0] += x1.y * wr.x; acc[5][1] += x1.y * wr.y; acc[5][2] += x1.y * wr.z; acc[5][3] += x1.y * wr.w;
            acc[6][0] += x1.z * wr.x; acc[6][1] += x1.z * wr.y; acc[6][2] += x1.z * wr.z; acc[6][3] += x1.z * wr.w;
            acc[7][0] += x1.w * wr.x; acc[7][1] += x1.w * wr.y; acc[7][2] += x1.w * wr.z; acc[7][3] += x1.w * wr.w;
        }
        buf ^= 1;
        __syncthreads();
    }

    float4 bv = bias ? *reinterpret_cast<const float4*>(bias + colBase + tx * 4) : z4;

    #pragma unroll
    for (int i = 0; i < 8; i++) {
        int row = rowBase + ty * 8 + i;
        if (row >= M) continue;
        float gate = 1.f;
        if (cnt) gate = (cnt[row] > 0) ? 1.f : 0.f;
        float4 o;
        o.x = acc[i][0] + bv.x * gate;
        o.y = acc[i][1] + bv.y * gate;
        o.z = acc[i][2] + bv.z * gate;
        o.w = acc[i][3] + bv.w * gate;
        if (doRelu) {
            o.x = fmaxf(o.x, 0.f); o.y = fmaxf(o.y, 0.f);
            o.z = fmaxf(o.z, 0.f); o.w = fmaxf(o.w, 0.f);
        }
        *reinterpret_cast<float4*>(C + (size_t)row * NOUT + colBase + tx * 4) = o;
    }
}

// ---------------- concat: xin = [state(64) | g(64) | emb[mode](16)] ----------------
__global__ void concat_kernel(const float* __restrict__ state, const float* __restrict__ g,
                              const float* __restrict__ emb, const int* __restrict__ mode,
                              float* __restrict__ xin, int n)
{
    int i = blockIdx.x * blockDim.x + threadIdx.x;
    int total = n * 144;
    if (i >= total) return;
    int node = i / 144;
    int c = i - node * 144;
    float v;
    if (c < 64)       v = state[(size_t)node * 64 + c];
    else if (c < 128) v = g[(size_t)node * 64 + (c - 64)];
    else {
        int m = mode[node];
        m = min(max(m, 0), 2);
        v = emb[(size_t)m * 16 + (c - 128)];
    }
    xin[i] = v;
}

// ---------------- heads ----------------
__global__ __launch_bounds__(256) void heads_kernel(
    const float* __restrict__ x2,
    const float* __restrict__ wm, const float* __restrict__ bm,
    const float* __restrict__ ws, const float* __restrict__ bs,
    float* __restrict__ out_mean, float* __restrict__ out_ls, int n)
{
    __shared__ float WmT[8 * 256];   // [o][k]
    __shared__ float WsT[8 * 256];
    for (int i = threadIdx.x; i < 2048; i += blockDim.x) {
        int o = i >> 8;
        int k = i & 255;
        WmT[i] = wm[k * 8 + o];
        WsT[i] = ws[k * 8 + o];
    }
    __syncthreads();
    int lane = threadIdx.x & 31;
    int w = threadIdx.x >> 5;
    int warpsPerBlock = blockDim.x >> 5;
    for (int node = blockIdx.x * warpsPerBlock + w; node < n; node += gridDim.x * warpsPerBlock) {
        float xv[8];
        #pragma unroll
        for (int c = 0; c < 8; c++) xv[c] = x2[(size_t)node * 256 + c * 32 + lane];
        float accM[8], accS[8];
        #pragma unroll
        for (int o = 0; o < 8; o++) { accM[o] = 0.f; accS[o] = 0.f; }
        #pragma unroll
        for (int c = 0; c < 8; c++) {
            int k = c * 32 + lane;
            #pragma unroll
            for (int o = 0; o < 8; o++) {
                accM[o] += xv[c] * WmT[o * 256 + k];
                accS[o] += xv[c] * WsT[o * 256 + k];
            }
        }
        #pragma unroll
        for (int o = 0; o < 8; o++) {
            #pragma unroll
            for (int d = 16; d > 0; d >>= 1) {
                accM[o] += __shfl_xor_sync(0xffffffffu, accM[o], d);
                accS[o] += __shfl_xor_sync(0xffffffffu, accS[o], d);
            }
        }
        if (lane == 0) {
            #pragma unroll
            for (int o = 0; o < 8; o++) {
                out_mean[(size_t)node * 8 + o] = accM[o] + bm[o];
                float lsv = accS[o] + bs[o];
                lsv = fminf(fmaxf(lsv, -20.f), 2.f);
                out_ls[(size_t)node * 8 + o] = lsv;
            }
        }
    }
}

// ---------------- launch ----------------
extern "C" void kernel_launch(void* const* d_in, const int* in_sizes, int n_in,
                              void* d_out, int out_size)
{
    const float* state  = (const float*)d_in[0];
    const float* xnodes = (const float*)d_in[1];
    const int*   edge   = (const int*)d_in[2];     // int32
    const int*   mode   = (const int*)d_in[3];
    const float* w_g1a = (const float*)d_in[4];
    const float* b_g1a = (const float*)d_in[5];
    const float* w_g1b = (const float*)d_in[6];
    const float* b_g1b = (const float*)d_in[7];
    const float* w_g2a = (const float*)d_in[8];
    const float* b_g2a = (const float*)d_in[9];
    const float* w_g2b = (const float*)d_in[10];
    const float* b_g2b = (const float*)d_in[11];
    const float* emb   = (const float*)d_in[12];
    const float* w1    = (const float*)d_in[13];
    const float* b1    = (const float*)d_in[14];
    const float* w2    = (const float*)d_in[15];
    const float* b2    = (const float*)d_in[16];
    const float* wm    = (const float*)d_in[17];
    const float* bm    = (const float*)d_in[18];
    const float* ws    = (const float*)d_in[19];
    const float* bs    = (const float*)d_in[20];

    const int N = in_sizes[0] / 64;     // 50000
    const int E = in_sizes[2] / 2;      // 800000
    const int* src = edge;
    const int* dst = edge + E;

    float *A1, *B1, *s1, *h, *A2, *B2, *s2, *g, *xin, *x1, *x2;
    int *cnt, *off, *cur, *srcs;
    cudaGetSymbolAddress((void**)&A1,   d_A1);
    cudaGetSymbolAddress((void**)&B1,   d_B1);
    cudaGetSymbolAddress((void**)&s1,   d_s1);
    cudaGetSymbolAddress((void**)&h,    d_h);
    cudaGetSymbolAddress((void**)&A2,   d_A2);
    cudaGetSymbolAddress((void**)&B2,   d_B2);
    cudaGetSymbolAddress((void**)&s2,   d_s2);
    cudaGetSymbolAddress((void**)&g,    d_g);
    cudaGetSymbolAddress((void**)&xin,  d_xin);
    cudaGetSymbolAddress((void**)&x1,   d_x1);
    cudaGetSymbolAddress((void**)&x2,   d_x2);
    cudaGetSymbolAddress((void**)&cnt,  d_cnt);
    cudaGetSymbolAddress((void**)&off,  d_off);
    cudaGetSymbolAddress((void**)&cur,  d_cur);
    cudaGetSymbolAddress((void**)&srcs, d_srcs);

    float* out_mean = (float*)d_out;
    float* out_ls   = (float*)d_out + (size_t)N * 8;

    // --- CSR by dst ---
    cudaMemsetAsync(cnt, 0, N * sizeof(int), 0);
    cudaMemsetAsync(cur, 0, N * sizeof(int), 0);
    hist_kernel<<<(E + 255) / 256, 256>>>(dst, cnt, E, N);
    scan_kernel<<<1, 1024>>>(cnt, off, N);
    scatter_kernel<<<(E + 255) / 256, 256>>>(src, dst, off, cur, srcs, E, N);

    dim3 tpb(256);
    int mBlocks = (N + 127) / 128;

    // --- Layer 1 ---
    gemm_kernel<<<dim3(2, mBlocks), tpb>>>(xnodes, w_g1a,            b_g1a, nullptr, A1, N, 64, 128, 0);
    gemm_kernel<<<dim3(2, mBlocks), tpb>>>(xnodes, w_g1a + 64 * 128, nullptr, nullptr, B1, N, 64, 128, 0);
    aggregate128<<<(N * 32 + 255) / 256, 256>>>(A1, B1, off, srcs, s1, N);
    gemm_kernel<<<dim3(2, mBlocks), tpb>>>(s1, w_g1b, b_g1b, cnt, h, N, 128, 128, 1);

    // --- Layer 2 ---
    gemm_kernel<<<dim3(1, mBlocks), tpb>>>(h, w_g2a,            b_g2a, nullptr, A2, N, 128, 64, 0);
    gemm_kernel<<<dim3(1, mBlocks), tpb>>>(h, w_g2a + 128 * 64, nullptr, nullptr, B2, N, 128, 64, 0);
    aggregate64<<<(N * 32 + 255) / 256, 256>>>(A2, B2, off, srcs, s2, N);
    gemm_kernel<<<dim3(1, mBlocks), tpb>>>(s2, w_g2b, b_g2b, cnt, g, N, 64, 64, 0);

    // --- MLP head ---
    concat_kernel<<<(N * 144 + 255) / 256, 256>>>(state, g, emb, mode, xin, N);
    gemm_kernel<<<dim3(4, mBlocks), tpb>>>(xin, w1, b1, nullptr, x1, N, 144, 256, 1);
    gemm_kernel<<<dim3(4, mBlocks), tpb>>>(x1,  w2, b2, nullptr, x2, N, 256, 256, 1);
    heads_kernel<<<(N + 7) / 8, 256>>>(x2, wm, bm, ws, bs, out_mean, out_ls, N);
}

// round 4
// speedup vs baseline: 1.3522x; 1.2995x over previous
#include <cuda_runtime.h>
#include <cuda_bf16.h>
#include <cstdint>

#define NMAX 50000
#define EMAX 800000

// ---------------- scratch ----------------
__device__ __align__(16) float d_A1[NMAX * 128];
__device__ __align__(16) float d_B1[NMAX * 128];
__device__ __align__(16) float d_s1[NMAX * 128];
__device__ __align__(16) float d_h [NMAX * 128];
__device__ __align__(16) float d_A2[NMAX * 64];
__device__ __align__(16) float d_B2[NMAX * 64];
__device__ __align__(16) float d_s2[NMAX * 64];
__device__ __align__(16) float d_g [NMAX * 64];
__device__ __align__(16) float d_xin[NMAX * 144];
__device__ __align__(16) float d_x1[NMAX * 256];
__device__ __align__(16) float d_x2[NMAX * 256];
__device__ int   d_cnt[NMAX];
__device__ int   d_off[NMAX + 1];
__device__ int   d_cur[NMAX];
__device__ int   d_srcs[EMAX];

// ---------------- CSR build ----------------
__global__ void hist_kernel(const int* __restrict__ dst, int* __restrict__ cnt, int E, int N)
{
    int e = blockIdx.x * blockDim.x + threadIdx.x;
    if (e < E) {
        int d = dst[e];
        d = min(max(d, 0), N - 1);
        atomicAdd(&cnt[d], 1);
    }
}

__global__ void scan_kernel(const int* __restrict__ cnt, int* __restrict__ off, int n)
{
    __shared__ int sh[1024];
    int tid = threadIdx.x;
    int carry = 0;
    for (int base = 0; base < n; base += 1024) {
        int i = base + tid;
        int v = (i < n) ? cnt[i] : 0;
        sh[tid] = v;
        __syncthreads();
        #pragma unroll
        for (int d = 1; d < 1024; d <<= 1) {
            int t = (tid >= d) ? sh[tid - d] : 0;
            __syncthreads();
            sh[tid] += t;
            __syncthreads();
        }
        if (i < n) off[i] = carry + sh[tid] - v;
        int tileSum = sh[1023];
        __syncthreads();
        carry += tileSum;
    }
    if (tid == 0) off[n] = carry;
}

__global__ void scatter_kernel(const int* __restrict__ src, const int* __restrict__ dst,
                               const int* __restrict__ off, int* __restrict__ cur,
                               int* __restrict__ out, int E, int N)
{
    int e = blockIdx.x * blockDim.x + threadIdx.x;
    if (e < E) {
        int d = dst[e];
        d = min(max(d, 0), N - 1);
        int s = src[e];
        s = min(max(s, 0), N - 1);
        int p = atomicAdd(&cur[d], 1);
        out[off[d] + p] = s;
    }
}

// ---------------- edge aggregation ----------------
__global__ void aggregate128(const float* __restrict__ A, const float* __restrict__ B,
                             const int* __restrict__ off, const int* __restrict__ srcs,
                             float* __restrict__ S, int n)
{
    int gw = (int)((blockIdx.x * blockDim.x + threadIdx.x) >> 5);
    int lane = threadIdx.x & 31;
    if (gw >= n) return;
    const float4* A4 = reinterpret_cast<const float4*>(A);
    const float4* B4 = reinterpret_cast<const float4*>(B);
    float4 a = A4[(size_t)gw * 32 + lane];
    float4 acc = make_float4(0.f, 0.f, 0.f, 0.f);
    int s = off[gw], e = off[gw + 1];
    for (int base = s; base < e; base += 32) {
        int m = e - base; if (m > 32) m = 32;
        int idx = (lane < m) ? srcs[base + lane] : 0;
        for (int j = 0; j < m; j++) {
            int sj = __shfl_sync(0xffffffffu, idx, j);
            float4 b = B4[(size_t)sj * 32 + lane];
            acc.x += fmaxf(a.x + b.x, 0.f);
            acc.y += fmaxf(a.y + b.y, 0.f);
            acc.z += fmaxf(a.z + b.z, 0.f);
            acc.w += fmaxf(a.w + b.w, 0.f);
        }
    }
    float inv = 1.f / fmaxf((float)(e - s), 1.f);
    float4 o = make_float4(acc.x * inv, acc.y * inv, acc.z * inv, acc.w * inv);
    reinterpret_cast<float4*>(S)[(size_t)gw * 32 + lane] = o;
}

__global__ void aggregate64(const float* __restrict__ A, const float* __restrict__ B,
                            const int* __restrict__ off, const int* __restrict__ srcs,
                            float* __restrict__ S, int n)
{
    int gw = (int)((blockIdx.x * blockDim.x + threadIdx.x) >> 5);
    int lane = threadIdx.x & 31;
    if (gw >= n) return;
    const float2* A2p = reinterpret_cast<const float2*>(A);
    const float2* B2p = reinterpret_cast<const float2*>(B);
    float2 a = A2p[(size_t)gw * 32 + lane];
    float2 acc = make_float2(0.f, 0.f);
    int s = off[gw], e = off[gw + 1];
    for (int base = s; base < e; base += 32) {
        int m = e - base; if (m > 32) m = 32;
        int idx = (lane < m) ? srcs[base + lane] : 0;
        for (int j = 0; j < m; j++) {
            int sj = __shfl_sync(0xffffffffu, idx, j);
            float2 b = B2p[(size_t)sj * 32 + lane];
            acc.x += fmaxf(a.x + b.x, 0.f);
            acc.y += fmaxf(a.y + b.y, 0.f);
        }
    }
    float inv = 1.f / fmaxf((float)(e - s), 1.f);
    float2 o = make_float2(acc.x * inv, acc.y * inv);
    reinterpret_cast<float2*>(S)[(size_t)gw * 32 + lane] = o;
}

// ---------------- tf32 helpers ----------------
__device__ __forceinline__ float to_tf32(float x) {
    unsigned u;
    asm("cvt.rna.tf32.f32 %0, %1;" : "=r"(u) : "f"(x));
    return __uint_as_float(u);
}

__device__ __forceinline__ void mma_tf32(float& c0, float& c1, float& c2, float& c3,
                                         unsigned a0, unsigned a1, unsigned a2, unsigned a3,
                                         unsigned b0, unsigned b1) {
    asm volatile(
        "mma.sync.aligned.m16n8k8.row.col.f32.tf32.tf32.f32 "
        "{%0,%1,%2,%3}, {%4,%5,%6,%7}, {%8,%9}, {%0,%1,%2,%3};"
        : "+f"(c0), "+f"(c1), "+f"(c2), "+f"(c3)
        : "r"(a0), "r"(a1), "r"(a2), "r"(a3), "r"(b0), "r"(b1));
}

// ---------------- tf32 tensor-core GEMM ----------------
// C = act(X[M,K] @ W[K,NOUT] + bias(gated)). K % 16 == 0, NOUT % 64 == 0.
// Block 256 thr = 8 warps; block tile 128x64; warp tile 32x32 (2 m16 x 4 n8).
#define XS_STRIDE 20   // (r*20+k) % 32 covers all banks for the A-frag quad pattern
#define WS_STRIDE 72   // 72 % 32 == 8: each k-row shifted 8 banks -> conflict-free B-frag
__global__ __launch_bounds__(256) void gemm_tc(
    const float* __restrict__ X, const float* __restrict__ W,
    const float* __restrict__ bias, const int* __restrict__ cnt,
    float* __restrict__ C, int M, int K, int NOUT, int doRelu)
{
    __shared__ __align__(16) float Xs[2][128][XS_STRIDE];
    __shared__ __align__(16) float Ws[2][16][WS_STRIDE];

    int t    = threadIdx.x;
    int lane = t & 31;
    int w    = t >> 5;
    int gid  = lane >> 2;        // 0..7
    int tig  = lane & 3;         // 0..3
    int warpRow = (w >> 1) * 32; // 0,32,64,96
    int warpCol = (w & 1) * 32;  // 0,32
    int rowBase = blockIdx.y * 128;
    int colBase = blockIdx.x * 64;

    // loaders
    int lr = t & 127;            // X tile row
    int lk = (t >> 7) * 8;       // 0 or 8
    int wk = t >> 4;             // 0..15
    int wc = (t & 15) * 4;       // 0..60

    const float* Xp = X + (size_t)(rowBase + lr) * K + lk;
    bool xvalid = (rowBase + lr) < M;
    const float4 z4 = make_float4(0.f, 0.f, 0.f, 0.f);

    float4 xa = xvalid ? *reinterpret_cast<const float4*>(Xp)     : z4;
    float4 xb = xvalid ? *reinterpret_cast<const float4*>(Xp + 4) : z4;
    float4 wv = *reinterpret_cast<const float4*>(W + (size_t)wk * NOUT + colBase + wc);

    float acc[2][4][4];
    #pragma unroll
    for (int m = 0; m < 2; m++)
        #pragma unroll
        for (int n = 0; n < 4; n++)
            #pragma unroll
            for (int q = 0; q < 4; q++) acc[m][n][q] = 0.f;

    int nk = K >> 4;
    int buf = 0;
    for (int ki = 0; ki < nk; ki++) {
        // commit (tf32-rounded) to smem
        {
            float4 xat = make_float4(to_tf32(xa.x), to_tf32(xa.y), to_tf32(xa.z), to_tf32(xa.w));
            float4 xbt = make_float4(to_tf32(xb.x), to_tf32(xb.y), to_tf32(xb.z), to_tf32(xb.w));
            float4 wvt = make_float4(to_tf32(wv.x), to_tf32(wv.y), to_tf32(wv.z), to_tf32(wv.w));
            *reinterpret_cast<float4*>(&Xs[buf][lr][lk])     = xat;
            *reinterpret_cast<float4*>(&Xs[buf][lr][lk + 4]) = xbt;
            *reinterpret_cast<float4*>(&Ws[buf][wk][wc])     = wvt;
        }
        __syncthreads();

        // prefetch next k-tile
        if (ki + 1 < nk) {
            int k0 = (ki + 1) * 16;
            xa = xvalid ? *reinterpret_cast<const float4*>(Xp + k0)     : z4;
            xb = xvalid ? *reinterpret_cast<const float4*>(Xp + k0 + 4) : z4;
            wv = *reinterpret_cast<const float4*>(W + (size_t)(k0 + wk) * NOUT + colBase + wc);
        }

        #pragma unroll
        for (int ks = 0; ks < 2; ks++) {
            int k0 = ks * 8;
            unsigned a[2][4], b[4][2];
            #pragma unroll
            for (int m = 0; m < 2; m++) {
                int r = warpRow + m * 16 + gid;
                a[m][0] = __float_as_uint(Xs[buf][r    ][k0 + tig]);
                a[m][1] = __float_as_uint(Xs[buf][r + 8][k0 + tig]);
                a[m][2] = __float_as_uint(Xs[buf][r    ][k0 + tig + 4]);
                a[m][3] = __float_as_uint(Xs[buf][r + 8][k0 + tig + 4]);
            }
            #pragma unroll
            for (int n = 0; n < 4; n++) {
                int c = warpCol + n * 8 + gid;
                b[n][0] = __float_as_uint(Ws[buf][k0 + tig    ][c]);
                b[n][1] = __float_as_uint(Ws[buf][k0 + tig + 4][c]);
            }
            #pragma unroll
            for (int m = 0; m < 2; m++)
                #pragma unroll
                for (int n = 0; n < 4; n++)
                    mma_tf32(acc[m][n][0], acc[m][n][1], acc[m][n][2], acc[m][n][3],
                             a[m][0], a[m][1], a[m][2], a[m][3], b[n][0], b[n][1]);
        }
        buf ^= 1;
        __syncthreads();
    }

    // epilogue: c0: (gid, 2*tig), c1: (gid, 2*tig+1), c2: (gid+8, 2*tig), c3: (gid+8, 2*tig+1)
    #pragma unroll
    for (int m = 0; m < 2; m++) {
        int r0 = rowBase + warpRow + m * 16 + gid;
        int r1 = r0 + 8;
        float gate0 = 1.f, gate1 = 1.f;
        if (cnt) {
            if (r0 < M) gate0 = (cnt[r0] > 0) ? 1.f : 0.f;
            if (r1 < M) gate1 = (cnt[r1] > 0) ? 1.f : 0.f;
        }
        #pragma unroll
        for (int n = 0; n < 4; n++) {
            int col = colBase + warpCol + n * 8 + tig * 2;
            float bx = 0.f, by = 0.f;
            if (bias) { bx = bias[col]; by = bias[col + 1]; }
            if (r0 < M) {
                float2 o;
                o.x = acc[m][n][0] + bx * gate0;
                o.y = acc[m][n][1] + by * gate0;
                if (doRelu) { o.x = fmaxf(o.x, 0.f); o.y = fmaxf(o.y, 0.f); }
                *reinterpret_cast<float2*>(C + (size_t)r0 * NOUT + col) = o;
            }
            if (r1 < M) {
                float2 o;
                o.x = acc[m][n][2] + bx * gate1;
                o.y = acc[m][n][3] + by * gate1;
                if (doRelu) { o.x = fmaxf(o.x, 0.f); o.y = fmaxf(o.y, 0.f); }
                *reinterpret_cast<float2*>(C + (size_t)r1 * NOUT + col) = o;
            }
        }
    }
}

// ---------------- concat ----------------
__global__ void concat_kernel(const float* __restrict__ state, const float* __restrict__ g,
                              const float* __restrict__ emb, const int* __restrict__ mode,
                              float* __restrict__ xin, int n)
{
    int i = blockIdx.x * blockDim.x + threadIdx.x;
    int total = n * 144;
    if (i >= total) return;
    int node = i / 144;
    int c = i - node * 144;
    float v;
    if (c < 64)       v = state[(size_t)node * 64 + c];
    else if (c < 128) v = g[(size_t)node * 64 + (c - 64)];
    else {
        int m = mode[node];
        m = min(max(m, 0), 2);
        v = emb[(size_t)m * 16 + (c - 128)];
    }
    xin[i] = v;
}

// ---------------- heads (fp32) ----------------
__global__ __launch_bounds__(256) void heads_kernel(
    const float* __restrict__ x2,
    const float* __restrict__ wm, const float* __restrict__ bm,
    const float* __restrict__ ws, const float* __restrict__ bs,
    float* __restrict__ out_mean, float* __restrict__ out_ls, int n)
{
    __shared__ float WmT[8 * 256];
    __shared__ float WsT[8 * 256];
    for (int i = threadIdx.x; i < 2048; i += blockDim.x) {
        int o = i >> 8;
        int k = i & 255;
        WmT[i] = wm[k * 8 + o];
        WsT[i] = ws[k * 8 + o];
    }
    __syncthreads();
    int lane = threadIdx.x & 31;
    int w = threadIdx.x >> 5;
    int warpsPerBlock = blockDim.x >> 5;
    for (int node = blockIdx.x * warpsPerBlock + w; node < n; node += gridDim.x * warpsPerBlock) {
        float xv[8];
        #pragma unroll
        for (int c = 0; c < 8; c++) xv[c] = x2[(size_t)node * 256 + c * 32 + lane];
        float accM[8], accS[8];
        #pragma unroll
        for (int o = 0; o < 8; o++) { accM[o] = 0.f; accS[o] = 0.f; }
        #pragma unroll
        for (int c = 0; c < 8; c++) {
            int k = c * 32 + lane;
            #pragma unroll
            for (int o = 0; o < 8; o++) {
                accM[o] += xv[c] * WmT[o * 256 + k];
                accS[o] += xv[c] * WsT[o * 256 + k];
            }
        }
        #pragma unroll
        for (int o = 0; o < 8; o++) {
            #pragma unroll
            for (int d = 16; d > 0; d >>= 1) {
                accM[o] += __shfl_xor_sync(0xffffffffu, accM[o], d);
                accS[o] += __shfl_xor_sync(0xffffffffu, accS[o], d);
            }
        }
        if (lane == 0) {
            #pragma unroll
            for (int o = 0; o < 8; o++) {
                out_mean[(size_t)node * 8 + o] = accM[o] + bm[o];
                float lsv = accS[o] + bs[o];
                lsv = fminf(fmaxf(lsv, -20.f), 2.f);
                out_ls[(size_t)node * 8 + o] = lsv;
            }
        }
    }
}

// ---------------- launch ----------------
extern "C" void kernel_launch(void* const* d_in, const int* in_sizes, int n_in,
                              void* d_out, int out_size)
{
    const float* state  = (const float*)d_in[0];
    const float* xnodes = (const float*)d_in[1];
    const int*   edge   = (const int*)d_in[2];
    const int*   mode   = (const int*)d_in[3];
    const float* w_g1a = (const float*)d_in[4];
    const float* b_g1a = (const float*)d_in[5];
    const float* w_g1b = (const float*)d_in[6];
    const float* b_g1b = (const float*)d_in[7];
    const float* w_g2a = (const float*)d_in[8];
    const float* b_g2a = (const float*)d_in[9];
    const float* w_g2b = (const float*)d_in[10];
    const float* b_g2b = (const float*)d_in[11];
    const float* emb   = (const float*)d_in[12];
    const float* w1    = (const float*)d_in[13];
    const float* b1    = (const float*)d_in[14];
    const float* w2    = (const float*)d_in[15];
    const float* b2    = (const float*)d_in[16];
    const float* wm    = (const float*)d_in[17];
    const float* bm    = (const float*)d_in[18];
    const float* ws    = (const float*)d_in[19];
    const float* bs    = (const float*)d_in[20];

    const int N = in_sizes[0] / 64;
    const int E = in_sizes[2] / 2;
    const int* src = edge;
    const int* dst = edge + E;

    float *A1, *B1, *s1, *h, *A2, *B2, *s2, *g, *xin, *x1, *x2;
    int *cnt, *off, *cur, *srcs;
    cudaGetSymbolAddress((void**)&A1,   d_A1);
    cudaGetSymbolAddress((void**)&B1,   d_B1);
    cudaGetSymbolAddress((void**)&s1,   d_s1);
    cudaGetSymbolAddress((void**)&h,    d_h);
    cudaGetSymbolAddress((void**)&A2,   d_A2);
    cudaGetSymbolAddress((void**)&B2,   d_B2);
    cudaGetSymbolAddress((void**)&s2,   d_s2);
    cudaGetSymbolAddress((void**)&g,    d_g);
    cudaGetSymbolAddress((void**)&xin,  d_xin);
    cudaGetSymbolAddress((void**)&x1,   d_x1);
    cudaGetSymbolAddress((void**)&x2,   d_x2);
    cudaGetSymbolAddress((void**)&cnt,  d_cnt);
    cudaGetSymbolAddress((void**)&off,  d_off);
    cudaGetSymbolAddress((void**)&cur,  d_cur);
    cudaGetSymbolAddress((void**)&srcs, d_srcs);

    float* out_mean = (float*)d_out;
    float* out_ls   = (float*)d_out + (size_t)N * 8;

    // --- CSR by dst ---
    cudaMemsetAsync(cnt, 0, N * sizeof(int), 0);
    cudaMemsetAsync(cur, 0, N * sizeof(int), 0);
    hist_kernel<<<(E + 255) / 256, 256>>>(dst, cnt, E, N);
    scan_kernel<<<1, 1024>>>(cnt, off, N);
    scatter_kernel<<<(E + 255) / 256, 256>>>(src, dst, off, cur, srcs, E, N);

    dim3 tpb(256);
    int mBlocks = (N + 127) / 128;

    // --- Layer 1 ---
    gemm_tc<<<dim3(2, mBlocks), tpb>>>(xnodes, w_g1a,            b_g1a, nullptr, A1, N, 64, 128, 0);
    gemm_tc<<<dim3(2, mBlocks), tpb>>>(xnodes, w_g1a + 64 * 128, nullptr, nullptr, B1, N, 64, 128, 0);
    aggregate128<<<(N * 32 + 255) / 256, 256>>>(A1, B1, off, srcs, s1, N);
    gemm_tc<<<dim3(2, mBlocks), tpb>>>(s1, w_g1b, b_g1b, cnt, h, N, 128, 128, 1);

    // --- Layer 2 ---
    gemm_tc<<<dim3(1, mBlocks), tpb>>>(h, w_g2a,            b_g2a, nullptr, A2, N, 128, 64, 0);
    gemm_tc<<<dim3(1, mBlocks), tpb>>>(h, w_g2a + 128 * 64, nullptr, nullptr, B2, N, 128, 64, 0);
    aggregate64<<<(N * 32 + 255) / 256, 256>>>(A2, B2, off, srcs, s2, N);
    gemm_tc<<<dim3(1, mBlocks), tpb>>>(s2, w_g2b, b_g2b, cnt, g, N, 64, 64, 0);

    // --- MLP head ---
    concat_kernel<<<(N * 144 + 255) / 256, 256>>>(state, g, emb, mode, xin, N);
    gemm_tc<<<dim3(4, mBlocks), tpb>>>(xin, w1, b1, nullptr, x1, N, 144, 256, 1);
    gemm_tc<<<dim3(4, mBlocks), tpb>>>(x1,  w2, b2, nullptr, x2, N, 256, 256, 1);
    heads_kernel<<<(N + 7) / 8, 256>>>(x2, wm, bm, ws, bs, out_mean, out_ls, N);
}

// round 5
// speedup vs baseline: 1.5276x; 1.1298x over previous
#include <cuda_runtime.h>
#include <cuda_bf16.h>
#include <cstdint>

#define NMAX 50000
#define EMAX 800000

// ---------------- scratch ----------------
__device__ __align__(16) float d_A1[NMAX * 128];
__device__ __align__(16) float d_B1[NMAX * 128];
__device__ __align__(16) float d_s1[NMAX * 128];
__device__ __align__(16) float d_h [NMAX * 128];
__device__ __align__(16) float d_A2[NMAX * 64];
__device__ __align__(16) float d_B2[NMAX * 64];
__device__ __align__(16) float d_s2[NMAX * 64];
__device__ __align__(16) float d_xin[NMAX * 144];
__device__ __align__(16) float d_x1[NMAX * 256];
__device__ __align__(16) float d_x2[NMAX * 256];
__device__ int   d_cnt[NMAX];
__device__ int   d_off[NMAX + 1];
__device__ int   d_cur[NMAX];
__device__ int   d_srcs[EMAX];

// ---------------- CSR build ----------------
__global__ void hist_kernel(const int* __restrict__ dst, int* __restrict__ cnt, int E, int N)
{
    int e = blockIdx.x * blockDim.x + threadIdx.x;
    if (e < E) {
        int d = dst[e];
        d = min(max(d, 0), N - 1);
        atomicAdd(&cnt[d], 1);
    }
}

__global__ void scan_kernel(const int* __restrict__ cnt, int* __restrict__ off, int n)
{
    __shared__ int sh[1024];
    int tid = threadIdx.x;
    int carry = 0;
    for (int base = 0; base < n; base += 1024) {
        int i = base + tid;
        int v = (i < n) ? cnt[i] : 0;
        sh[tid] = v;
        __syncthreads();
        #pragma unroll
        for (int d = 1; d < 1024; d <<= 1) {
            int t = (tid >= d) ? sh[tid - d] : 0;
            __syncthreads();
            sh[tid] += t;
            __syncthreads();
        }
        if (i < n) off[i] = carry + sh[tid] - v;
        int tileSum = sh[1023];
        __syncthreads();
        carry += tileSum;
    }
    if (tid == 0) off[n] = carry;
}

__global__ void scatter_kernel(const int* __restrict__ src, const int* __restrict__ dst,
                               const int* __restrict__ off, int* __restrict__ cur,
                               int* __restrict__ out, int E, int N)
{
    int e = blockIdx.x * blockDim.x + threadIdx.x;
    if (e < E) {
        int d = dst[e];
        d = min(max(d, 0), N - 1);
        int s = src[e];
        s = min(max(s, 0), N - 1);
        int p = atomicAdd(&cur[d], 1);
        out[off[d] + p] = s;
    }
}

// ---------------- edge aggregation ----------------
__global__ void aggregate128(const float* __restrict__ A, const float* __restrict__ B,
                             const int* __restrict__ off, const int* __restrict__ srcs,
                             float* __restrict__ S, int n)
{
    int gw = (int)((blockIdx.x * blockDim.x + threadIdx.x) >> 5);
    int lane = threadIdx.x & 31;
    if (gw >= n) return;
    const float4* A4 = reinterpret_cast<const float4*>(A);
    const float4* B4 = reinterpret_cast<const float4*>(B);
    float4 a = A4[(size_t)gw * 32 + lane];
    float4 acc = make_float4(0.f, 0.f, 0.f, 0.f);
    int s = off[gw], e = off[gw + 1];
    for (int base = s; base < e; base += 32) {
        int m = e - base; if (m > 32) m = 32;
        int idx = (lane < m) ? srcs[base + lane] : 0;
        for (int j = 0; j < m; j++) {
            int sj = __shfl_sync(0xffffffffu, idx, j);
            float4 b = B4[(size_t)sj * 32 + lane];
            acc.x += fmaxf(a.x + b.x, 0.f);
            acc.y += fmaxf(a.y + b.y, 0.f);
            acc.z += fmaxf(a.z + b.z, 0.f);
            acc.w += fmaxf(a.w + b.w, 0.f);
        }
    }
    float inv = 1.f / fmaxf((float)(e - s), 1.f);
    float4 o = make_float4(acc.x * inv, acc.y * inv, acc.z * inv, acc.w * inv);
    reinterpret_cast<float4*>(S)[(size_t)gw * 32 + lane] = o;
}

__global__ void aggregate64(const float* __restrict__ A, const float* __restrict__ B,
                            const int* __restrict__ off, const int* __restrict__ srcs,
                            float* __restrict__ S, int n)
{
    int gw = (int)((blockIdx.x * blockDim.x + threadIdx.x) >> 5);
    int lane = threadIdx.x & 31;
    if (gw >= n) return;
    const float2* A2p = reinterpret_cast<const float2*>(A);
    const float2* B2p = reinterpret_cast<const float2*>(B);
    float2 a = A2p[(size_t)gw * 32 + lane];
    float2 acc = make_float2(0.f, 0.f);
    int s = off[gw], e = off[gw + 1];
    for (int base = s; base < e; base += 32) {
        int m = e - base; if (m > 32) m = 32;
        int idx = (lane < m) ? srcs[base + lane] : 0;
        for (int j = 0; j < m; j++) {
            int sj = __shfl_sync(0xffffffffu, idx, j);
            float2 b = B2p[(size_t)sj * 32 + lane];
            acc.x += fmaxf(a.x + b.x, 0.f);
            acc.y += fmaxf(a.y + b.y, 0.f);
        }
    }
    float inv = 1.f / fmaxf((float)(e - s), 1.f);
    float2 o = make_float2(acc.x * inv, acc.y * inv);
    reinterpret_cast<float2*>(S)[(size_t)gw * 32 + lane] = o;
}

// ---------------- tf32 helpers ----------------
__device__ __forceinline__ float to_tf32(float x) {
    unsigned u;
    asm("cvt.rna.tf32.f32 %0, %1;" : "=r"(u) : "f"(x));
    return __uint_as_float(u);
}

__device__ __forceinline__ void mma_tf32(float& c0, float& c1, float& c2, float& c3,
                                         unsigned a0, unsigned a1, unsigned a2, unsigned a3,
                                         unsigned b0, unsigned b1) {
    asm volatile(
        "mma.sync.aligned.m16n8k8.row.col.f32.tf32.tf32.f32 "
        "{%0,%1,%2,%3}, {%4,%5,%6,%7}, {%8,%9}, {%0,%1,%2,%3};"
        : "+f"(c0), "+f"(c1), "+f"(c2), "+f"(c3)
        : "r"(a0), "r"(a1), "r"(a2), "r"(a3), "r"(b0), "r"(b1));
}

#define XS_STRIDE 20
#define WS_STRIDE_128 136   // 136 % 32 == 8
#define WS_STRIDE_64  72    // 72  % 32 == 8

// ---------------- gemm128: block tile 128x128, 8 warps, warp tile 32x64 ----------------
// Dual-W: column blocks cb < splitBlk use (W0,bias0,C0), else (W1,bias1,C1) with cb -= splitBlk.
// C row stride = ldc. K % 16 == 0.
__global__ __launch_bounds__(256) void gemm128(
    const float* __restrict__ X,
    const float* __restrict__ W0, const float* __restrict__ W1,
    const float* __restrict__ bias0, const float* __restrict__ bias1,
    const int* __restrict__ cnt,
    float* __restrict__ C0, float* __restrict__ C1,
    int M, int K, int NOUT, int ldc, int splitBlk, int doRelu)
{
    __shared__ __align__(16) float Xs[2][128][XS_STRIDE];
    __shared__ __align__(16) float Ws[2][16][WS_STRIDE_128];

    int t    = threadIdx.x;
    int lane = t & 31;
    int w    = t >> 5;
    int gid  = lane >> 2;
    int tig  = lane & 3;
    int warpRow = (w >> 1) * 32;   // 0,32,64,96
    int warpCol = (w & 1) * 64;    // 0,64
    int rowBase = blockIdx.y * 128;

    int cb = blockIdx.x;
    const float* W    = W0;
    const float* bias = bias0;
    float*       C    = C0;
    if (cb >= splitBlk) { W = W1; bias = bias1; C = C1; cb -= splitBlk; }
    int colBase = cb * 128;

    int lr = t & 127;
    int lk = (t >> 7) * 8;
    int wk = t >> 4;
    int wc = (t & 15) * 4;

    const float* Xp = X + (size_t)(rowBase + lr) * K + lk;
    bool xvalid = (rowBase + lr) < M;
    const float4 z4 = make_float4(0.f, 0.f, 0.f, 0.f);

    float4 xa = xvalid ? *reinterpret_cast<const float4*>(Xp)     : z4;
    float4 xb = xvalid ? *reinterpret_cast<const float4*>(Xp + 4) : z4;
    float4 wv0 = *reinterpret_cast<const float4*>(W + (size_t)wk * NOUT + colBase + wc);
    float4 wv1 = *reinterpret_cast<const float4*>(W + (size_t)wk * NOUT + colBase + wc + 64);

    float acc[2][8][4];
    #pragma unroll
    for (int m = 0; m < 2; m++)
        #pragma unroll
        for (int n = 0; n < 8; n++)
            #pragma unroll
            for (int q = 0; q < 4; q++) acc[m][n][q] = 0.f;

    int nk = K >> 4;
    int buf = 0;
    for (int ki = 0; ki < nk; ki++) {
        {
            float4 xat = make_float4(to_tf32(xa.x), to_tf32(xa.y), to_tf32(xa.z), to_tf32(xa.w));
            float4 xbt = make_float4(to_tf32(xb.x), to_tf32(xb.y), to_tf32(xb.z), to_tf32(xb.w));
            float4 w0t = make_float4(to_tf32(wv0.x), to_tf32(wv0.y), to_tf32(wv0.z), to_tf32(wv0.w));
            float4 w1t = make_float4(to_tf32(wv1.x), to_tf32(wv1.y), to_tf32(wv1.z), to_tf32(wv1.w));
            *reinterpret_cast<float4*>(&Xs[buf][lr][lk])      = xat;
            *reinterpret_cast<float4*>(&Xs[buf][lr][lk + 4])  = xbt;
            *reinterpret_cast<float4*>(&Ws[buf][wk][wc])      = w0t;
            *reinterpret_cast<float4*>(&Ws[buf][wk][wc + 64]) = w1t;
        }
        __syncthreads();

        if (ki + 1 < nk) {
            int k0 = (ki + 1) * 16;
            xa = xvalid ? *reinterpret_cast<const float4*>(Xp + k0)     : z4;
            xb = xvalid ? *reinterpret_cast<const float4*>(Xp + k0 + 4) : z4;
            wv0 = *reinterpret_cast<const float4*>(W + (size_t)(k0 + wk) * NOUT + colBase + wc);
            wv1 = *reinterpret_cast<const float4*>(W + (size_t)(k0 + wk) * NOUT + colBase + wc + 64);
        }

        #pragma unroll
        for (int ks = 0; ks < 2; ks++) {
            int k0 = ks * 8;
            unsigned a[2][4], b[8][2];
            #pragma unroll
            for (int m = 0; m < 2; m++) {
                int r = warpRow + m * 16 + gid;
                a[m][0] = __float_as_uint(Xs[buf][r    ][k0 + tig]);
                a[m][1] = __float_as_uint(Xs[buf][r + 8][k0 + tig]);
                a[m][2] = __float_as_uint(Xs[buf][r    ][k0 + tig + 4]);
                a[m][3] = __float_as_uint(Xs[buf][r + 8][k0 + tig + 4]);
            }
            #pragma unroll
            for (int n = 0; n < 8; n++) {
                int c = warpCol + n * 8 + gid;
                b[n][0] = __float_as_uint(Ws[buf][k0 + tig    ][c]);
                b[n][1] = __float_as_uint(Ws[buf][k0 + tig + 4][c]);
            }
            #pragma unroll
            for (int m = 0; m < 2; m++)
                #pragma unroll
                for (int n = 0; n < 8; n++)
                    mma_tf32(acc[m][n][0], acc[m][n][1], acc[m][n][2], acc[m][n][3],
                             a[m][0], a[m][1], a[m][2], a[m][3], b[n][0], b[n][1]);
        }
        buf ^= 1;
        __syncthreads();
    }

    #pragma unroll
    for (int m = 0; m < 2; m++) {
        int r0 = rowBase + warpRow + m * 16 + gid;
        int r1 = r0 + 8;
        float gate0 = 1.f, gate1 = 1.f;
        if (cnt) {
            if (r0 < M) gate0 = (cnt[r0] > 0) ? 1.f : 0.f;
            if (r1 < M) gate1 = (cnt[r1] > 0) ? 1.f : 0.f;
        }
        #pragma unroll
        for (int n = 0; n < 8; n++) {
            int col = colBase + warpCol + n * 8 + tig * 2;
            float bx = 0.f, by = 0.f;
            if (bias) { bx = bias[col]; by = bias[col + 1]; }
            if (r0 < M) {
                float2 o;
                o.x = acc[m][n][0] + bx * gate0;
                o.y = acc[m][n][1] + by * gate0;
                if (doRelu) { o.x = fmaxf(o.x, 0.f); o.y = fmaxf(o.y, 0.f); }
                *reinterpret_cast<float2*>(C + (size_t)r0 * ldc + col) = o;
            }
            if (r1 < M) {
                float2 o;
                o.x = acc[m][n][2] + bx * gate1;
                o.y = acc[m][n][3] + by * gate1;
                if (doRelu) { o.x = fmaxf(o.x, 0.f); o.y = fmaxf(o.y, 0.f); }
                *reinterpret_cast<float2*>(C + (size_t)r1 * ldc + col) = o;
            }
        }
    }
}

// ---------------- gemm64: block tile 128x64, 8 warps, warp tile 32x32 ----------------
__global__ __launch_bounds__(256) void gemm64(
    const float* __restrict__ X,
    const float* __restrict__ W0, const float* __restrict__ W1,
    const float* __restrict__ bias0, const float* __restrict__ bias1,
    const int* __restrict__ cnt,
    float* __restrict__ C0, float* __restrict__ C1,
    int M, int K, int NOUT, int ldc, int splitBlk, int doRelu)
{
    __shared__ __align__(16) float Xs[2][128][XS_STRIDE];
    __shared__ __align__(16) float Ws[2][16][WS_STRIDE_64];

    int t    = threadIdx.x;
    int lane = t & 31;
    int w    = t >> 5;
    int gid  = lane >> 2;
    int tig  = lane & 3;
    int warpRow = (w >> 1) * 32;
    int warpCol = (w & 1) * 32;
    int rowBase = blockIdx.y * 128;

    int cb = blockIdx.x;
    const float* W    = W0;
    const float* bias = bias0;
    float*       C    = C0;
    if (cb >= splitBlk) { W = W1; bias = bias1; C = C1; cb -= splitBlk; }
    int colBase = cb * 64;

    int lr = t & 127;
    int lk = (t >> 7) * 8;
    int wk = t >> 4;
    int wc = (t & 15) * 4;

    const float* Xp = X + (size_t)(rowBase + lr) * K + lk;
    bool xvalid = (rowBase + lr) < M;
    const float4 z4 = make_float4(0.f, 0.f, 0.f, 0.f);

    float4 xa = xvalid ? *reinterpret_cast<const float4*>(Xp)     : z4;
    float4 xb = xvalid ? *reinterpret_cast<const float4*>(Xp + 4) : z4;
    float4 wv = *reinterpret_cast<const float4*>(W + (size_t)wk * NOUT + colBase + wc);

    float acc[2][4][4];
    #pragma unroll
    for (int m = 0; m < 2; m++)
        #pragma unroll
        for (int n = 0; n < 4; n++)
            #pragma unroll
            for (int q = 0; q < 4; q++) acc[m][n][q] = 0.f;

    int nk = K >> 4;
    int buf = 0;
    for (int ki = 0; ki < nk; ki++) {
        {
            float4 xat = make_float4(to_tf32(xa.x), to_tf32(xa.y), to_tf32(xa.z), to_tf32(xa.w));
            float4 xbt = make_float4(to_tf32(xb.x), to_tf32(xb.y), to_tf32(xb.z), to_tf32(xb.w));
            float4 wvt = make_float4(to_tf32(wv.x), to_tf32(wv.y), to_tf32(wv.z), to_tf32(wv.w));
            *reinterpret_cast<float4*>(&Xs[buf][lr][lk])     = xat;
            *reinterpret_cast<float4*>(&Xs[buf][lr][lk + 4]) = xbt;
            *reinterpret_cast<float4*>(&Ws[buf][wk][wc])     = wvt;
        }
        __syncthreads();

        if (ki + 1 < nk) {
            int k0 = (ki + 1) * 16;
            xa = xvalid ? *reinterpret_cast<const float4*>(Xp + k0)     : z4;
            xb = xvalid ? *reinterpret_cast<const float4*>(Xp + k0 + 4) : z4;
            wv = *reinterpret_cast<const float4*>(W + (size_t)(k0 + wk) * NOUT + colBase + wc);
        }

        #pragma unroll
        for (int ks = 0; ks < 2; ks++) {
            int k0 = ks * 8;
            unsigned a[2][4], b[4][2];
            #pragma unroll
            for (int m = 0; m < 2; m++) {
                int r = warpRow + m * 16 + gid;
                a[m][0] = __float_as_uint(Xs[buf][r    ][k0 + tig]);
                a[m][1] = __float_as_uint(Xs[buf][r + 8][k0 + tig]);
                a[m][2] = __float_as_uint(Xs[buf][r    ][k0 + tig + 4]);
                a[m][3] = __float_as_uint(Xs[buf][r + 8][k0 + tig + 4]);
            }
            #pragma unroll
            for (int n = 0; n < 4; n++) {
                int c = warpCol + n * 8 + gid;
                b[n][0] = __float_as_uint(Ws[buf][k0 + tig    ][c]);
                b[n][1] = __float_as_uint(Ws[buf][k0 + tig + 4][c]);
            }
            #pragma unroll
            for (int m = 0; m < 2; m++)
                #pragma unroll
                for (int n = 0; n < 4; n++)
                    mma_tf32(acc[m][n][0], acc[m][n][1], acc[m][n][2], acc[m][n][3],
                             a[m][0], a[m][1], a[m][2], a[m][3], b[n][0], b[n][1]);
        }
        buf ^= 1;
        __syncthreads();
    }

    #pragma unroll
    for (int m = 0; m < 2; m++) {
        int r0 = rowBase + warpRow + m * 16 + gid;
        int r1 = r0 + 8;
        float gate0 = 1.f, gate1 = 1.f;
        if (cnt) {
            if (r0 < M) gate0 = (cnt[r0] > 0) ? 1.f : 0.f;
            if (r1 < M) gate1 = (cnt[r1] > 0) ? 1.f : 0.f;
        }
        #pragma unroll
        for (int n = 0; n < 4; n++) {
            int col = colBase + warpCol + n * 8 + tig * 2;
            float bx = 0.f, by = 0.f;
            if (bias) { bx = bias[col]; by = bias[col + 1]; }
            if (r0 < M) {
                float2 o;
                o.x = acc[m][n][0] + bx * gate0;
                o.y = acc[m][n][1] + by * gate0;
                if (doRelu) { o.x = fmaxf(o.x, 0.f); o.y = fmaxf(o.y, 0.f); }
                *reinterpret_cast<float2*>(C + (size_t)r0 * ldc + col) = o;
            }
            if (r1 < M) {
                float2 o;
                o.x = acc[m][n][2] + bx * gate1;
                o.y = acc[m][n][3] + by * gate1;
                if (doRelu) { o.x = fmaxf(o.x, 0.f); o.y = fmaxf(o.y, 0.f); }
                *reinterpret_cast<float2*>(C + (size_t)r1 * ldc + col) = o;
            }
        }
    }
}

// ---------------- fill xin cols [0:64)=state, [128:144)=emb[mode] ----------------
__global__ void fill_xin_kernel(const float* __restrict__ state, const float* __restrict__ emb,
                                const int* __restrict__ mode, float* __restrict__ xin, int n)
{
    int i = blockIdx.x * blockDim.x + threadIdx.x;   // n*20 float4 slots per node
    int total = n * 20;
    if (i >= total) return;
    int node = i / 20;
    int q = i - node * 20;
    const float4* s4;
    float4 v;
    if (q < 16) {
        s4 = reinterpret_cast<const float4*>(state + (size_t)node * 64);
        v = s4[q];
        reinterpret_cast<float4*>(xin + (size_t)node * 144)[q] = v;
    } else {
        int m = mode[node];
        m = min(max(m, 0), 2);
        s4 = reinterpret_cast<const float4*>(emb + (size_t)m * 16);
        v = s4[q - 16];
        *reinterpret_cast<float4*>(xin + (size_t)node * 144 + 128 + (q - 16) * 4) = v;
    }
}

// ---------------- heads ----------------
__global__ __launch_bounds__(256) void heads_kernel(
    const float* __restrict__ x2,
    const float* __restrict__ wm, const float* __restrict__ bm,
    const float* __restrict__ ws, const float* __restrict__ bs,
    float* __restrict__ out_mean, float* __restrict__ out_ls, int n)
{
    __shared__ float WmT[8 * 256];
    __shared__ float WsT[8 * 256];
    for (int i = threadIdx.x; i < 2048; i += blockDim.x) {
        int o = i >> 8;
        int k = i & 255;
        WmT[i] = wm[k * 8 + o];
        WsT[i] = ws[k * 8 + o];
    }
    __syncthreads();
    int lane = threadIdx.x & 31;
    int w = threadIdx.x >> 5;
    int warpsPerBlock = blockDim.x >> 5;
    for (int node = blockIdx.x * warpsPerBlock + w; node < n; node += gridDim.x * warpsPerBlock) {
        float xv[8];
        #pragma unroll
        for (int c = 0; c < 8; c++) xv[c] = x2[(size_t)node * 256 + c * 32 + lane];
        float accM[8], accS[8];
        #pragma unroll
        for (int o = 0; o < 8; o++) { accM[o] = 0.f; accS[o] = 0.f; }
        #pragma unroll
        for (int c = 0; c < 8; c++) {
            int k = c * 32 + lane;
            #pragma unroll
            for (int o = 0; o < 8; o++) {
                accM[o] += xv[c] * WmT[o * 256 + k];
                accS[o] += xv[c] * WsT[o * 256 + k];
            }
        }
        #pragma unroll
        for (int o = 0; o < 8; o++) {
            #pragma unroll
            for (int d = 16; d > 0; d >>= 1) {
                accM[o] += __shfl_xor_sync(0xffffffffu, accM[o], d);
                accS[o] += __shfl_xor_sync(0xffffffffu, accS[o], d);
            }
        }
        if (lane == 0) {
            #pragma unroll
            for (int o = 0; o < 8; o++) {
                out_mean[(size_t)node * 8 + o] = accM[o] + bm[o];
                float lsv = accS[o] + bs[o];
                lsv = fminf(fmaxf(lsv, -20.f), 2.f);
                out_ls[(size_t)node * 8 + o] = lsv;
            }
        }
    }
}

// ---------------- launch ----------------
extern "C" void kernel_launch(void* const* d_in, const int* in_sizes, int n_in,
                              void* d_out, int out_size)
{
    const float* state  = (const float*)d_in[0];
    const float* xnodes = (const float*)d_in[1];
    const int*   edge   = (const int*)d_in[2];
    const int*   mode   = (const int*)d_in[3];
    const float* w_g1a = (const float*)d_in[4];
    const float* b_g1a = (const float*)d_in[5];
    const float* w_g1b = (const float*)d_in[6];
    const float* b_g1b = (const float*)d_in[7];
    const float* w_g2a = (const float*)d_in[8];
    const float* b_g2a = (const float*)d_in[9];
    const float* w_g2b = (const float*)d_in[10];
    const float* b_g2b = (const float*)d_in[11];
    const float* emb   = (const float*)d_in[12];
    const float* w1    = (const float*)d_in[13];
    const float* b1    = (const float*)d_in[14];
    const float* w2    = (const float*)d_in[15];
    const float* b2    = (const float*)d_in[16];
    const float* wm    = (const float*)d_in[17];
    const float* bm    = (const float*)d_in[18];
    const float* ws    = (const float*)d_in[19];
    const float* bs    = (const float*)d_in[20];

    const int N = in_sizes[0] / 64;
    const int E = in_sizes[2] / 2;
    const int* src = edge;
    const int* dst = edge + E;

    float *A1, *B1, *s1, *h, *A2, *B2, *s2, *xin, *x1, *x2;
    int *cnt, *off, *cur, *srcs;
    cudaGetSymbolAddress((void**)&A1,   d_A1);
    cudaGetSymbolAddress((void**)&B1,   d_B1);
    cudaGetSymbolAddress((void**)&s1,   d_s1);
    cudaGetSymbolAddress((void**)&h,    d_h);
    cudaGetSymbolAddress((void**)&A2,   d_A2);
    cudaGetSymbolAddress((void**)&B2,   d_B2);
    cudaGetSymbolAddress((void**)&s2,   d_s2);
    cudaGetSymbolAddress((void**)&xin,  d_xin);
    cudaGetSymbolAddress((void**)&x1,   d_x1);
    cudaGetSymbolAddress((void**)&x2,   d_x2);
    cudaGetSymbolAddress((void**)&cnt,  d_cnt);
    cudaGetSymbolAddress((void**)&off,  d_off);
    cudaGetSymbolAddress((void**)&cur,  d_cur);
    cudaGetSymbolAddress((void**)&srcs, d_srcs);

    float* out_mean = (float*)d_out;
    float* out_ls   = (float*)d_out + (size_t)N * 8;

    // --- CSR by dst ---
    cudaMemsetAsync(cnt, 0, N * sizeof(int), 0);
    cudaMemsetAsync(cur, 0, N * sizeof(int), 0);
    hist_kernel<<<(E + 255) / 256, 256>>>(dst, cnt, E, N);
    scan_kernel<<<1, 1024>>>(cnt, off, N);
    scatter_kernel<<<(E + 255) / 256, 256>>>(src, dst, off, cur, srcs, E, N);

    dim3 tpb(256);
    int mBlocks = (N + 127) / 128;

    // xin static parts (independent of GNN) — launch early
    fill_xin_kernel<<<(N * 20 + 255) / 256, 256>>>(state, emb, mode, xin, N);

    // --- Layer 1: fused A1|B1 = x @ {wa_top, wa_bot} ---
    gemm128<<<dim3(2, mBlocks), tpb>>>(xnodes, w_g1a, w_g1a + 64 * 128, b_g1a, nullptr,
                                       nullptr, A1, B1, N, 64, 128, 128, 1, 0);
    aggregate128<<<(N * 32 + 255) / 256, 256>>>(A1, B1, off, srcs, s1, N);
    gemm128<<<dim3(1, mBlocks), tpb>>>(s1, w_g1b, w_g1b, b_g1b, nullptr,
                                       cnt, h, h, N, 128, 128, 128, 1, 1);

    // --- Layer 2: fused A2|B2 = h @ {w2a_top, w2a_bot} ---
    gemm64<<<dim3(2, mBlocks), tpb>>>(h, w_g2a, w_g2a + 128 * 64, b_g2a, nullptr,
                                      nullptr, A2, B2, N, 128, 64, 64, 1, 0);
    aggregate64<<<(N * 32 + 255) / 256, 256>>>(A2, B2, off, srcs, s2, N);
    // g written directly into xin[:,64:128] (ldc=144)
    gemm64<<<dim3(1, mBlocks), tpb>>>(s2, w_g2b, w_g2b, b_g2b, nullptr,
                                      cnt, xin + 64, xin + 64, N, 64, 64, 144, 1, 0);

    // --- MLP head ---
    gemm128<<<dim3(2, mBlocks), tpb>>>(xin, w1, w1, b1, nullptr,
                                       nullptr, x1, x1, N, 144, 256, 256, 2, 1);
    gemm128<<<dim3(2, mBlocks), tpb>>>(x1, w2, w2, b2, nullptr,
                                       nullptr, x2, x2, N, 256, 256, 256, 2, 1);
    heads_kernel<<<(N + 7) / 8, 256>>>(x2, wm, bm, ws, bs, out_mean, out_ls, N);
}

// round 7
// speedup vs baseline: 1.8600x; 1.2175x over previous
#include <cuda_runtime.h>
#include <cuda_bf16.h>
#include <cstdint>

#define NMAX 50000
#define EMAX 800000

// ---------------- scratch ----------------
__device__ __align__(16) float d_A1[NMAX * 128];
__device__ __align__(16) float d_B1[NMAX * 128];
__device__ __align__(16) float d_s1[NMAX * 128];
__device__ __align__(16) float d_h [NMAX * 128];
__device__ __align__(16) float d_A2[NMAX * 64];
__device__ __align__(16) float d_B2[NMAX * 64];
__device__ __align__(16) float d_s2[NMAX * 64];
__device__ __align__(16) float d_xin[NMAX * 144];
__device__ __align__(16) float d_x1[NMAX * 256];
__device__ __align__(16) float d_x2[NMAX * 256];
__device__ __align__(16) float d_xr[NMAX * 64];
__device__ __align__(16) float d_wbuf[155648];
__device__ int   d_cnt[NMAX];
__device__ int   d_off[NMAX + 1];
__device__ int   d_cur[NMAX];
__device__ int   d_srcs[EMAX];

// weight buffer offsets (rounded tf32 copies)
#define WB_G1A 0        // 128*128
#define WB_G1B 16384    // 128*128
#define WB_G2A 32768    // 256*64
#define WB_G2B 49152    // 64*64
#define WB_W1  53248    // 144*256
#define WB_W2  90112    // 256*256

// ---------------- tf32 helpers ----------------
__device__ __forceinline__ float to_tf32(float x) {
    unsigned u;
    asm("cvt.rna.tf32.f32 %0, %1;" : "=r"(u) : "f"(x));
    return __uint_as_float(u);
}

__device__ __forceinline__ void mma_tf32(float& c0, float& c1, float& c2, float& c3,
                                         unsigned a0, unsigned a1, unsigned a2, unsigned a3,
                                         unsigned b0, unsigned b1) {
    asm volatile(
        "mma.sync.aligned.m16n8k8.row.col.f32.tf32.tf32.f32 "
        "{%0,%1,%2,%3}, {%4,%5,%6,%7}, {%8,%9}, {%0,%1,%2,%3};"
        : "+f"(c0), "+f"(c1), "+f"(c2), "+f"(c3)
        : "r"(a0), "r"(a1), "r"(a2), "r"(a3), "r"(b0), "r"(b1));
}

__device__ __forceinline__ void cp_async16(void* smem, const void* gmem, bool valid) {
    uint32_t sa = (uint32_t)__cvta_generic_to_shared(smem);
    int sz = valid ? 16 : 0;
    asm volatile("cp.async.cg.shared.global [%0], [%1], 16, %2;"
                 :: "r"(sa), "l"(gmem), "r"(sz));
}
#define CP_COMMIT()  asm volatile("cp.async.commit_group;")
#define CP_WAIT_1()  asm volatile("cp.async.wait_group 1;")
#define CP_WAIT_0()  asm volatile("cp.async.wait_group 0;")

// ---------------- CSR build ----------------
__global__ void hist_kernel(const int* __restrict__ dst, int* __restrict__ cnt, int E, int N)
{
    int e = blockIdx.x * blockDim.x + threadIdx.x;
    if (e < E) {
        int d = dst[e];
        d = min(max(d, 0), N - 1);
        atomicAdd(&cnt[d], 1);
    }
}

// single-block exclusive scan, shfl warp-scan
__global__ void scan_kernel(const int* __restrict__ cnt, int* __restrict__ off, int n)
{
    __shared__ int wsums[32];
    int tid = threadIdx.x, lane = tid & 31, wid = tid >> 5;
    int carry = 0;
    for (int base = 0; base < n; base += 1024) {
        int i = base + tid;
        int v = (i < n) ? cnt[i] : 0;
        int x = v;
        #pragma unroll
        for (int d = 1; d < 32; d <<= 1) {
            int t = __shfl_up_sync(0xffffffffu, x, d);
            if (lane >= d) x += t;
        }
        if (lane == 31) wsums[wid] = x;
        __syncthreads();
        if (wid == 0) {
            int s = wsums[lane];
            #pragma unroll
            for (int d = 1; d < 32; d <<= 1) {
                int t = __shfl_up_sync(0xffffffffu, s, d);
                if (lane >= d) s += t;
            }
            wsums[lane] = s;
        }
        __syncthreads();
        int add = wid ? wsums[wid - 1] : 0;
        if (i < n) off[i] = carry + add + x - v;   // exclusive
        int tile = wsums[31];
        __syncthreads();
        carry += tile;
    }
    if (tid == 0) off[n] = carry;
}

__global__ void scatter_kernel(const int* __restrict__ src, const int* __restrict__ dst,
                               const int* __restrict__ off, int* __restrict__ cur,
                               int* __restrict__ out, int E, int N)
{
    int e = blockIdx.x * blockDim.x + threadIdx.x;
    if (e < E) {
        int d = dst[e];
        d = min(max(d, 0), N - 1);
        int s = src[e];
        s = min(max(s, 0), N - 1);
        int p = atomicAdd(&cur[d], 1);
        out[off[d] + p] = s;
    }
}

// ---------------- edge aggregation (outputs tf32-rounded) ----------------
__global__ void aggregate128(const float* __restrict__ A, const float* __restrict__ B,
                             const int* __restrict__ off, const int* __restrict__ srcs,
                             float* __restrict__ S, int n)
{
    int gw = (int)((blockIdx.x * blockDim.x + threadIdx.x) >> 5);
    int lane = threadIdx.x & 31;
    if (gw >= n) return;
    const float4* A4 = reinterpret_cast<const float4*>(A);
    const float4* B4 = reinterpret_cast<const float4*>(B);
    float4 a = A4[(size_t)gw * 32 + lane];
    float4 acc = make_float4(0.f, 0.f, 0.f, 0.f);
    int s = off[gw], e = off[gw + 1];
    for (int base = s; base < e; base += 32) {
        int m = e - base; if (m > 32) m = 32;
        int idx = (lane < m) ? srcs[base + lane] : 0;
        for (int j = 0; j < m; j++) {
            int sj = __shfl_sync(0xffffffffu, idx, j);
            float4 b = B4[(size_t)sj * 32 + lane];
            acc.x += fmaxf(a.x + b.x, 0.f);
            acc.y += fmaxf(a.y + b.y, 0.f);
            acc.z += fmaxf(a.z + b.z, 0.f);
            acc.w += fmaxf(a.w + b.w, 0.f);
        }
    }
    float inv = 1.f / fmaxf((float)(e - s), 1.f);
    float4 o = make_float4(to_tf32(acc.x * inv), to_tf32(acc.y * inv),
                           to_tf32(acc.z * inv), to_tf32(acc.w * inv));
    reinterpret_cast<float4*>(S)[(size_t)gw * 32 + lane] = o;
}

__global__ void aggregate64(const float* __restrict__ A, const float* __restrict__ B,
                            const int* __restrict__ off, const int* __restrict__ srcs,
                            float* __restrict__ S, int n)
{
    int gw = (int)((blockIdx.x * blockDim.x + threadIdx.x) >> 5);
    int lane = threadIdx.x & 31;
    if (gw >= n) return;
    const float2* A2p = reinterpret_cast<const float2*>(A);
    const float2* B2p = reinterpret_cast<const float2*>(B);
    float2 a = A2p[(size_t)gw * 32 + lane];
    float2 acc = make_float2(0.f, 0.f);
    int s = off[gw], e = off[gw + 1];
    for (int base = s; base < e; base += 32) {
        int m = e - base; if (m > 32) m = 32;
        int idx = (lane < m) ? srcs[base + lane] : 0;
        for (int j = 0; j < m; j++) {
            int sj = __shfl_sync(0xffffffffu, idx, j);
            float2 b = B2p[(size_t)sj * 32 + lane];
            acc.x += fmaxf(a.x + b.x, 0.f);
            acc.y += fmaxf(a.y + b.y, 0.f);
        }
    }
    float inv = 1.f / fmaxf((float)(e - s), 1.f);
    float2 o = make_float2(to_tf32(acc.x * inv), to_tf32(acc.y * inv));
    reinterpret_cast<float2*>(S)[(size_t)gw * 32 + lane] = o;
}

// ---------------- prep: round weights + xnodes to tf32 ----------------
struct RJobs { const float* src[6]; float* dst[6]; int count[6]; };
__global__ void round_jobs_kernel(RJobs jb)
{
    int j = blockIdx.y;
    int count = jb.count[j];
    const float* s = jb.src[j];
    float* d = jb.dst[j];
    for (int i = blockIdx.x * blockDim.x + threadIdx.x; i < count; i += gridDim.x * blockDim.x)
        d[i] = to_tf32(s[i]);
}

__global__ void round4_kernel(const float4* __restrict__ s, float4* __restrict__ d, int n4)
{
    int i = blockIdx.x * blockDim.x + threadIdx.x;
    if (i < n4) {
        float4 v = s[i];
        d[i] = make_float4(to_tf32(v.x), to_tf32(v.y), to_tf32(v.z), to_tf32(v.w));
    }
}

// ---------------- fill xin cols [0:64)=tf32(state), [128:144)=tf32(emb[mode]) ----------------
__global__ void fill_xin_kernel(const float* __restrict__ state, const float* __restrict__ emb,
                                const int* __restrict__ mode, float* __restrict__ xin, int n)
{
    int i = blockIdx.x * blockDim.x + threadIdx.x;
    int total = n * 20;
    if (i >= total) return;
    int node = i / 20;
    int q = i - node * 20;
    float4 v;
    if (q < 16) {
        v = reinterpret_cast<const float4*>(state + (size_t)node * 64)[q];
        v = make_float4(to_tf32(v.x), to_tf32(v.y), to_tf32(v.z), to_tf32(v.w));
        reinterpret_cast<float4*>(xin + (size_t)node * 144)[q] = v;
    } else {
        int m = mode[node];
        m = min(max(m, 0), 2);
        v = reinterpret_cast<const float4*>(emb + (size_t)m * 16)[q - 16];
        v = make_float4(to_tf32(v.x), to_tf32(v.y), to_tf32(v.z), to_tf32(v.w));
        *reinterpret_cast<float4*>(xin + (size_t)node * 144 + 128 + (q - 16) * 4) = v;
    }
}

// ---------------- async tf32 GEMM, 3-stage cp.async pipeline ----------------
// Block tile 128 x CTN, 8 warps, warp tile 32 x (CTN/2). Inputs pre-rounded tf32.
// flags: bit0 = relu, bit1 = round output to tf32.
template<int CTN>
__global__ __launch_bounds__(256) void gemm_async(
    const float* __restrict__ X,
    const float* __restrict__ W0, const float* __restrict__ W1,
    const float* __restrict__ bias0, const float* __restrict__ bias1,
    const int* __restrict__ cnt,
    float* __restrict__ C0, float* __restrict__ C1,
    int M, int K, int NOUT, int ldc, int splitBlk, int flags)
{
    constexpr int WS = CTN + 8;
    constexpr int S  = 3;
    constexpr int NB = CTN / 16;
    __shared__ __align__(16) float Xs[S][128][20];
    __shared__ __align__(16) float Ws[S][16][WS];

    int t    = threadIdx.x;
    int lane = t & 31;
    int w    = t >> 5;
    int gid  = lane >> 2;
    int tig  = lane & 3;
    int warpRow = (w >> 1) * 32;
    int warpCol = (w & 1) * (CTN / 2);
    int rowBase = blockIdx.y * 128;

    int cb = blockIdx.x;
    const float* W    = W0;
    const float* bias = bias0;
    float*       C    = C0;
    if (cb >= splitBlk) { W = W1; bias = bias1; C = C1; cb -= splitBlk; }
    int colBase = cb * CTN;

    int xr = t >> 2;
    int xq = (t & 3) * 4;
    bool v0 = (rowBase + xr) < M;
    bool v1 = (rowBase + xr + 64) < M;
    const float* Xp0 = X + (size_t)(rowBase + xr) * K + xq;
    const float* Xp1 = X + (size_t)(rowBase + xr + 64) * K + xq;

    int nk = K >> 4;

    auto issue = [&](int s) {
        int b = s % S;
        int k0 = s * 16;
        cp_async16(&Xs[b][xr][xq],      Xp0 + k0, v0);
        cp_async16(&Xs[b][xr + 64][xq], Xp1 + k0, v1);
        if (CTN == 128) {
            int kr = t >> 5, wc = (t & 31) * 4;
            cp_async16(&Ws[b][kr][wc],     W + (size_t)(k0 + kr) * NOUT + colBase + wc, true);
            cp_async16(&Ws[b][kr + 8][wc], W + (size_t)(k0 + kr + 8) * NOUT + colBase + wc, true);
        } else {
            int kr = t >> 4, wc = (t & 15) * 4;
            cp_async16(&Ws[b][kr][wc],     W + (size_t)(k0 + kr) * NOUT + colBase + wc, true);
        }
        CP_COMMIT();
    };

    issue(0);
    issue(1);

    float acc[2][NB][4];
    #pragma unroll
    for (int m = 0; m < 2; m++)
        #pragma unroll
        for (int n = 0; n < NB; n++)
            #pragma unroll
            for (int q = 0; q < 4; q++) acc[m][n][q] = 0.f;

    for (int ki = 0; ki < nk; ki++) {
        // Tail-correct wait: if no further issue follows, drain everything —
        // otherwise wait_group 1 would leave THIS iteration's buffer in flight.
        if (ki + S - 1 < nk) {
            CP_WAIT_1();
            __syncthreads();
            issue(ki + S - 1);
        } else {
            CP_WAIT_0();
            __syncthreads();
        }
        int buf = ki % S;

        #pragma unroll
        for (int ks = 0; ks < 2; ks++) {
            int k0 = ks * 8;
            unsigned a[2][4], b[NB][2];
            #pragma unroll
            for (int m = 0; m < 2; m++) {
                int r = warpRow + m * 16 + gid;
                a[m][0] = __float_as_uint(Xs[buf][r    ][k0 + tig]);
                a[m][1] = __float_as_uint(Xs[buf][r + 8][k0 + tig]);
                a[m][2] = __float_as_uint(Xs[buf][r    ][k0 + tig + 4]);
                a[m][3] = __float_as_uint(Xs[buf][r + 8][k0 + tig + 4]);
            }
            #pragma unroll
            for (int n = 0; n < NB; n++) {
                int c = warpCol + n * 8 + gid;
                b[n][0] = __float_as_uint(Ws[buf][k0 + tig    ][c]);
                b[n][1] = __float_as_uint(Ws[buf][k0 + tig + 4][c]);
            }
            #pragma unroll
            for (int m = 0; m < 2; m++)
                #pragma unroll
                for (int n = 0; n < NB; n++)
                    mma_tf32(acc[m][n][0], acc[m][n][1], acc[m][n][2], acc[m][n][3],
                             a[m][0], a[m][1], a[m][2], a[m][3], b[n][0], b[n][1]);
        }
    }

    bool doRelu  = flags & 1;
    bool doRound = flags & 2;

    #pragma unroll
    for (int m = 0; m < 2; m++) {
        int r0 = rowBase + warpRow + m * 16 + gid;
        int r1 = r0 + 8;
        float gate0 = 1.f, gate1 = 1.f;
        if (cnt) {
            if (r0 < M) gate0 = (cnt[r0] > 0) ? 1.f : 0.f;
            if (r1 < M) gate1 = (cnt[r1] > 0) ? 1.f : 0.f;
        }
        #pragma unroll
        for (int n = 0; n < NB; n++) {
            int col = colBase + warpCol + n * 8 + tig * 2;
            float bx = 0.f, by = 0.f;
            if (bias) { bx = bias[col]; by = bias[col + 1]; }
            if (r0 < M) {
                float2 o;
                o.x = acc[m][n][0] + bx * gate0;
                o.y = acc[m][n][1] + by * gate0;
                if (doRelu)  { o.x = fmaxf(o.x, 0.f); o.y = fmaxf(o.y, 0.f); }
                if (doRound) { o.x = to_tf32(o.x); o.y = to_tf32(o.y); }
                *reinterpret_cast<float2*>(C + (size_t)r0 * ldc + col) = o;
            }
            if (r1 < M) {
                float2 o;
                o.x = acc[m][n][2] + bx * gate1;
                o.y = acc[m][n][3] + by * gate1;
                if (doRelu)  { o.x = fmaxf(o.x, 0.f); o.y = fmaxf(o.y, 0.f); }
                if (doRound) { o.x = to_tf32(o.x); o.y = to_tf32(o.y); }
                *reinterpret_cast<float2*>(C + (size_t)r1 * ldc + col) = o;
            }
        }
    }
}

// ---------------- heads (fp32) ----------------
__global__ __launch_bounds__(256) void heads_kernel(
    const float* __restrict__ x2,
    const float* __restrict__ wm, const float* __restrict__ bm,
    const float* __restrict__ ws, const float* __restrict__ bs,
    float* __restrict__ out_mean, float* __restrict__ out_ls, int n)
{
    __shared__ float WmT[8 * 256];
    __shared__ float WsT[8 * 256];
    for (int i = threadIdx.x; i < 2048; i += blockDim.x) {
        int o = i >> 8;
        int k = i & 255;
        WmT[i] = wm[k * 8 + o];
        WsT[i] = ws[k * 8 + o];
    }
    __syncthreads();
    int lane = threadIdx.x & 31;
    int w = threadIdx.x >> 5;
    int warpsPerBlock = blockDim.x >> 5;
    for (int node = blockIdx.x * warpsPerBlock + w; node < n; node += gridDim.x * warpsPerBlock) {
        float xv[8];
        #pragma unroll
        for (int c = 0; c < 8; c++) xv[c] = x2[(size_t)node * 256 + c * 32 + lane];
        float accM[8], accS[8];
        #pragma unroll
        for (int o = 0; o < 8; o++) { accM[o] = 0.f; accS[o] = 0.f; }
        #pragma unroll
        for (int c = 0; c < 8; c++) {
            int k = c * 32 + lane;
            #pragma unroll
            for (int o = 0; o < 8; o++) {
                accM[o] += xv[c] * WmT[o * 256 + k];
                accS[o] += xv[c] * WsT[o * 256 + k];
            }
        }
        #pragma unroll
        for (int o = 0; o < 8; o++) {
            #pragma unroll
            for (int d = 16; d > 0; d >>= 1) {
                accM[o] += __shfl_xor_sync(0xffffffffu, accM[o], d);
                accS[o] += __shfl_xor_sync(0xffffffffu, accS[o], d);
            }
        }
        if (lane == 0) {
            #pragma unroll
            for (int o = 0; o < 8; o++) {
                out_mean[(size_t)node * 8 + o] = accM[o] + bm[o];
                float lsv = accS[o] + bs[o];
                lsv = fminf(fmaxf(lsv, -20.f), 2.f);
                out_ls[(size_t)node * 8 + o] = lsv;
            }
        }
    }
}

// ---------------- launch ----------------
extern "C" void kernel_launch(void* const* d_in, const int* in_sizes, int n_in,
                              void* d_out, int out_size)
{
    const float* state  = (const float*)d_in[0];
    const float* xnodes = (const float*)d_in[1];
    const int*   edge   = (const int*)d_in[2];
    const int*   mode   = (const int*)d_in[3];
    const float* w_g1a = (const float*)d_in[4];
    const float* b_g1a = (const float*)d_in[5];
    const float* w_g1b = (const float*)d_in[6];
    const float* b_g1b = (const float*)d_in[7];
    const float* w_g2a = (const float*)d_in[8];
    const float* b_g2a = (const float*)d_in[9];
    const float* w_g2b = (const float*)d_in[10];
    const float* b_g2b = (const float*)d_in[11];
    const float* emb   = (const float*)d_in[12];
    const float* w1    = (const float*)d_in[13];
    const float* b1    = (const float*)d_in[14];
    const float* w2    = (const float*)d_in[15];
    const float* b2    = (const float*)d_in[16];
    const float* wm    = (const float*)d_in[17];
    const float* bm    = (const float*)d_in[18];
    const float* ws    = (const float*)d_in[19];
    const float* bs    = (const float*)d_in[20];

    const int N = in_sizes[0] / 64;
    const int E = in_sizes[2] / 2;
    const int* src = edge;
    const int* dst = edge + E;

    float *A1, *B1, *s1, *h, *A2, *B2, *s2, *xin, *x1, *x2, *xr, *wb;
    int *cnt, *off, *cur, *srcs;
    cudaGetSymbolAddress((void**)&A1,   d_A1);
    cudaGetSymbolAddress((void**)&B1,   d_B1);
    cudaGetSymbolAddress((void**)&s1,   d_s1);
    cudaGetSymbolAddress((void**)&h,    d_h);
    cudaGetSymbolAddress((void**)&A2,   d_A2);
    cudaGetSymbolAddress((void**)&B2,   d_B2);
    cudaGetSymbolAddress((void**)&s2,   d_s2);
    cudaGetSymbolAddress((void**)&xin,  d_xin);
    cudaGetSymbolAddress((void**)&x1,   d_x1);
    cudaGetSymbolAddress((void**)&x2,   d_x2);
    cudaGetSymbolAddress((void**)&xr,   d_xr);
    cudaGetSymbolAddress((void**)&wb,   d_wbuf);
    cudaGetSymbolAddress((void**)&cnt,  d_cnt);
    cudaGetSymbolAddress((void**)&off,  d_off);
    cudaGetSymbolAddress((void**)&cur,  d_cur);
    cudaGetSymbolAddress((void**)&srcs, d_srcs);

    float* out_mean = (float*)d_out;
    float* out_ls   = (float*)d_out + (size_t)N * 8;

    // --- CSR by dst ---
    cudaMemsetAsync(cnt, 0, N * sizeof(int), 0);
    cudaMemsetAsync(cur, 0, N * sizeof(int), 0);
    hist_kernel<<<(E + 255) / 256, 256>>>(dst, cnt, E, N);
    scan_kernel<<<1, 1024>>>(cnt, off, N);
    scatter_kernel<<<(E + 255) / 256, 256>>>(src, dst, off, cur, srcs, E, N);

    // --- prep ---
    RJobs jb;
    jb.src[0] = w_g1a; jb.dst[0] = wb + WB_G1A; jb.count[0] = 128 * 128;
    jb.src[1] = w_g1b; jb.dst[1] = wb + WB_G1B; jb.count[1] = 128 * 128;
    jb.src[2] = w_g2a; jb.dst[2] = wb + WB_G2A; jb.count[2] = 256 * 64;
    jb.src[3] = w_g2b; jb.dst[3] = wb + WB_G2B; jb.count[3] = 64 * 64;
    jb.src[4] = w1;    jb.dst[4] = wb + WB_W1;  jb.count[4] = 144 * 256;
    jb.src[5] = w2;    jb.dst[5] = wb + WB_W2;  jb.count[5] = 256 * 256;
    round_jobs_kernel<<<dim3(64, 6), 256>>>(jb);
    round4_kernel<<<(N * 16 + 255) / 256, 256>>>((const float4*)xnodes, (float4*)xr, N * 16);
    fill_xin_kernel<<<(N * 20 + 255) / 256, 256>>>(state, emb, mode, xin, N);

    dim3 tpb(256);
    int mBlocks = (N + 127) / 128;

    // --- Layer 1 ---
    gemm_async<128><<<dim3(2, mBlocks), tpb>>>(xr, wb + WB_G1A, wb + WB_G1A + 64 * 128,
                                               b_g1a, nullptr, nullptr, A1, B1,
                                               N, 64, 128, 128, 1, 0);
    aggregate128<<<(N * 32 + 255) / 256, 256>>>(A1, B1, off, srcs, s1, N);
    gemm_async<128><<<dim3(1, mBlocks), tpb>>>(s1, wb + WB_G1B, wb + WB_G1B,
                                               b_g1b, nullptr, cnt, h, h,
                                               N, 128, 128, 128, 1, 3);

    // --- Layer 2 ---
    gemm_async<64><<<dim3(2, mBlocks), tpb>>>(h, wb + WB_G2A, wb + WB_G2A + 128 * 64,
                                              b_g2a, nullptr, nullptr, A2, B2,
                                              N, 128, 64, 64, 1, 0);
    aggregate64<<<(N * 32 + 255) / 256, 256>>>(A2, B2, off, srcs, s2, N);
    gemm_async<64><<<dim3(1, mBlocks), tpb>>>(s2, wb + WB_G2B, wb + WB_G2B,
                                              b_g2b, nullptr, cnt, xin + 64, xin + 64,
                                              N, 64, 64, 144, 1, 2);

    // --- MLP head ---
    gemm_async<128><<<dim3(2, mBlocks), tpb>>>(xin, wb + WB_W1, wb + WB_W1,
                                               b1, nullptr, nullptr, x1, x1,
                                               N, 144, 256, 256, 2, 3);
    gemm_async<128><<<dim3(2, mBlocks), tpb>>>(x1, wb + WB_W2, wb + WB_W2,
                                               b2, nullptr, nullptr, x2, x2,
                                               N, 256, 256, 256, 2, 1);
    heads_kernel<<<(N + 7) / 8, 256>>>(x2, wm, bm, ws, bs, out_mean, out_ls, N);
}